// round 2
// baseline (speedup 1.0000x reference)
#include <cuda_runtime.h>
#include <cuda_bf16.h>
#include <math.h>

// ---------------------------------------------------------------------------
// IterativeBlock: h[8,2048,1024] fp32
//   4x { z = rmsnorm(h); combined = [z, shift(z)];
//        h += sigmoid(ls_fg(combined)) * ls_gu(combined) }
//   z = rmsnorm(h); ff = silu(ls_ffg(z)) * ls_fff(z); out = h + ls_ffp(ff)
//   ls(x) = blockdiag(W) x + A (B x), NUM_BLOCKS = 8
//
// Per-token decomposition of the combined input:
//   blockdiag blocks 0-3 read z_t[(b)*256 ..], blocks 4-7 read z_{t-1}[(b-4)*256 ..]
//   rank-32 B splits into B[:, :1024] (z_t) and B[:, 1024:] (z_{t-1})
// ---------------------------------------------------------------------------

#define NTOK 16384           // 8 * 2048 tokens
#define EPSF 1.1920929e-07f

// scratch (static device globals; heap allocation is forbidden)
__device__ float g_H [NTOK * 1024];
__device__ float g_Z [NTOK * 1024];
__device__ float g_R [NTOK * 64];
__device__ float g_FF[NTOK * 2816];

__device__ __forceinline__ float sigf(float x) { return 1.0f / (1.0f + __expf(-x)); }

__device__ __forceinline__ float dot4(float4 a, float4 b, float acc) {
    acc = fmaf(a.x, b.x, acc);
    acc = fmaf(a.y, b.y, acc);
    acc = fmaf(a.z, b.z, acc);
    acc = fmaf(a.w, b.w, acc);
    return acc;
}

// ---------------------------------------------------------------------------
// k_rms: z[t] = h[t] * rsqrt(mean(h[t]^2) + eps).  One CTA per token.
// ---------------------------------------------------------------------------
__global__ __launch_bounds__(256)
void k_rms(const float* __restrict__ h, float* __restrict__ z) {
    __shared__ float ws[8];
    const int t = blockIdx.x, tid = threadIdx.x;
    float4 v = __ldg((const float4*)(h + (size_t)t * 1024) + tid);
    float s = v.x * v.x + v.y * v.y + v.z * v.z + v.w * v.w;
#pragma unroll
    for (int off = 16; off; off >>= 1) s += __shfl_xor_sync(0xffffffffu, s, off);
    if ((tid & 31) == 0) ws[tid >> 5] = s;
    __syncthreads();
    if (tid < 32) {
        float x2 = (tid < 8) ? ws[tid] : 0.0f;
#pragma unroll
        for (int off = 4; off; off >>= 1) x2 += __shfl_xor_sync(0xffffffffu, x2, off);
        if (tid == 0) ws[0] = rsqrtf(x2 * (1.0f / 1024.0f) + EPSF);
    }
    __syncthreads();
    const float inv = ws[0];
    float4 o = make_float4(v.x * inv, v.y * inv, v.z * inv, v.w * inv);
    *((float4*)(z + (size_t)t * 1024) + tid) = o;
}

// ---------------------------------------------------------------------------
// k_rank: R[t, 0:32] = B1 @ in_t ; R[t, 32:64] = B2 @ in_t  (NO=64)
//         R[t, 0:32] = B1 @ in_t                            (NO=32)
// in_t = [Z[t], Z[t-1]] (SHIFT, KD=2048) or src[t] (KD = SRCSTRIDE).
// Tile: 64 tokens x NO outputs, 256 threads, K-chunks of 32.
// Xs/Bs stored transposed ([k][t]/[k][o], stride 65/NO+1) -> coalesced gmem
// reads and conflict-free smem.
// ---------------------------------------------------------------------------
template<int NO, int KD, int SRCSTRIDE, bool SHIFT>
__global__ __launch_bounds__(256)
void k_rank(const float* __restrict__ src,
            const float* __restrict__ B1, const float* __restrict__ B2,
            float* __restrict__ R) {
    constexpr int TX = NO / 4;        // threads along outputs
    constexpr int TY = 256 / TX;      // thread groups along tokens
    constexpr int TP = 64 / TY;       // tokens per thread
    __shared__ float Xs[32 * 65];
    __shared__ float Bs[32 * (NO + 1)];

    const int tid = threadIdx.x;
    const int t0  = blockIdx.x * 64;
    const int tx  = tid % TX, ty = tid / TX;
    const int o0  = tx * 4, tl0 = ty * TP;

    float acc[TP][4];
#pragma unroll
    for (int j = 0; j < TP; j++)
#pragma unroll
        for (int i = 0; i < 4; i++) acc[j][i] = 0.0f;

    for (int kc = 0; kc < KD; kc += 32) {
        __syncthreads();
        int roff = 0, col = kc;
        if (SHIFT && kc >= 1024) { roff = -1; col = kc - 1024; }
        // X tile (transposed): 64 tokens x 32 k
        for (int idx = tid; idx < 64 * 32; idx += 256) {
            int k = idx & 31, tl = idx >> 5;
            float v = 0.0f;
            if (!SHIFT || roff == 0 || ((t0 + tl) & 2047) != 0)
                v = __ldg(src + (size_t)(t0 + tl + roff) * SRCSTRIDE + col + k);
            Xs[k * 65 + tl] = v;
        }
        // B tile (transposed): 32 k x NO outputs
        for (int idx = tid; idx < 32 * NO; idx += 256) {
            int k = idx & 31, o = idx >> 5;
            float v = (o < 32) ? __ldg(B1 + (size_t)o * KD + kc + k)
                               : __ldg(B2 + (size_t)(o - 32) * KD + kc + k);
            Bs[k * (NO + 1) + o] = v;
        }
        __syncthreads();
#pragma unroll
        for (int k = 0; k < 32; k++) {
            float bv[4];
#pragma unroll
            for (int i = 0; i < 4; i++) bv[i] = Bs[k * (NO + 1) + o0 + i];
#pragma unroll
            for (int j = 0; j < TP; j++) {
                float xv = Xs[k * 65 + tl0 + j];
#pragma unroll
                for (int i = 0; i < 4; i++) acc[j][i] = fmaf(xv, bv[i], acc[j][i]);
            }
        }
    }
#pragma unroll
    for (int j = 0; j < TP; j++)
#pragma unroll
        for (int i = 0; i < 4; i++)
            R[(size_t)(t0 + tl0 + j) * 64 + o0 + i] = acc[j][i];
}

// ---------------------------------------------------------------------------
// k_iter: per CTA = 64 tokens x blockdiag block b (128 outputs).
// Computes both fg and gu: blockdiag(W)@x + A@R, then
// hout = hin + sigmoid(yg) * yu.
// ---------------------------------------------------------------------------
#define ITER_SMEM ((64 * 260 + 64 * 64) * 4)
__global__ __launch_bounds__(256)
void k_iter(const float* __restrict__ Z, const float* __restrict__ R,
            const float* __restrict__ Wg, const float* __restrict__ Wu,
            const float* __restrict__ Ag, const float* __restrict__ Au,
            const float* __restrict__ hin, float* __restrict__ hout) {
    extern __shared__ float sm[];
    float* Xs = sm;                 // 64 x 260 (padded)
    float* Rs = sm + 64 * 260;      // 64 x 64
    const int tid = threadIdx.x;
    const int t0  = blockIdx.x * 64;
    const int b   = blockIdx.y;
    const int roff  = (b < 4) ? 0 : -1;
    const int cbase = (b & 3) * 256;

    for (int idx = tid; idx < 64 * 64; idx += 256) {
        int tl = idx >> 6, k4 = idx & 63;
        float4 v = make_float4(0.f, 0.f, 0.f, 0.f);
        if (roff == 0 || ((t0 + tl) & 2047) != 0)
            v = __ldg((const float4*)(Z + (size_t)(t0 + tl + roff) * 1024 + cbase) + k4);
        *(float4*)(Xs + tl * 260 + k4 * 4) = v;
    }
    for (int idx = tid; idx < 64 * 64; idx += 256)
        Rs[idx] = __ldg(R + (size_t)t0 * 64 + idx);
    __syncthreads();

    const int tx = tid & 31, ty = tid >> 5;
    const int o = tx * 4;
    const int orow = b * 128 + o;
    float accg[8][4], accu[8][4];
#pragma unroll
    for (int j = 0; j < 8; j++)
#pragma unroll
        for (int i = 0; i < 4; i++) { accg[j][i] = 0.f; accu[j][i] = 0.f; }

    const float4* Wg4 = (const float4*)Wg + (size_t)orow * 64;   // rows of 256 floats
    const float4* Wu4 = (const float4*)Wu + (size_t)orow * 64;
    for (int k4 = 0; k4 < 64; k4++) {
        float4 wg[4], wu[4];
#pragma unroll
        for (int i = 0; i < 4; i++) {
            wg[i] = __ldg(Wg4 + i * 64 + k4);
            wu[i] = __ldg(Wu4 + i * 64 + k4);
        }
#pragma unroll
        for (int j = 0; j < 8; j++) {
            float4 xv = *(const float4*)(Xs + (ty * 8 + j) * 260 + k4 * 4);
#pragma unroll
            for (int i = 0; i < 4; i++) {
                accg[j][i] = dot4(wg[i], xv, accg[j][i]);
                accu[j][i] = dot4(wu[i], xv, accu[j][i]);
            }
        }
    }

    const float4* Ag4 = (const float4*)Ag + (size_t)orow * 8;    // rows of 32 floats
    const float4* Au4 = (const float4*)Au + (size_t)orow * 8;
#pragma unroll
    for (int r4 = 0; r4 < 8; r4++) {
        float4 av[4], bv[4];
#pragma unroll
        for (int i = 0; i < 4; i++) {
            av[i] = __ldg(Ag4 + i * 8 + r4);
            bv[i] = __ldg(Au4 + i * 8 + r4);
        }
#pragma unroll
        for (int j = 0; j < 8; j++) {
            float4 rg = *(const float4*)(Rs + (ty * 8 + j) * 64 + r4 * 4);
            float4 ru = *(const float4*)(Rs + (ty * 8 + j) * 64 + 32 + r4 * 4);
#pragma unroll
            for (int i = 0; i < 4; i++) {
                accg[j][i] = dot4(av[i], rg, accg[j][i]);
                accu[j][i] = dot4(bv[i], ru, accu[j][i]);
            }
        }
    }

#pragma unroll
    for (int j = 0; j < 8; j++) {
        int tg = t0 + ty * 8 + j;
        float4 hv = __ldg((const float4*)(hin + (size_t)tg * 1024 + orow));
        float4 ov;
        ov.x = fmaf(sigf(accg[j][0]), accu[j][0], hv.x);
        ov.y = fmaf(sigf(accg[j][1]), accu[j][1], hv.y);
        ov.z = fmaf(sigf(accg[j][2]), accu[j][2], hv.z);
        ov.w = fmaf(sigf(accg[j][3]), accu[j][3], hv.w);
        *(float4*)(hout + (size_t)tg * 1024 + orow) = ov;
    }
}

// ---------------------------------------------------------------------------
// k_ff: per CTA = 64 tokens x (block b, out-tile ot of 128 within 352 outs).
// FF = silu(ls_ffg(z)) * ls_fff(z).  K = 128.
// ---------------------------------------------------------------------------
#define FF_SMEM ((64 * 132 + 64 * 64) * 4)
__global__ __launch_bounds__(256)
void k_ff(const float* __restrict__ Z, const float* __restrict__ R,
          const float* __restrict__ Wg, const float* __restrict__ Wf,
          const float* __restrict__ Ag, const float* __restrict__ Af,
          float* __restrict__ FF) {
    extern __shared__ float sm[];
    float* Xs = sm;                 // 64 x 132 (padded)
    float* Rs = sm + 64 * 132;      // 64 x 64
    const int tid = threadIdx.x;
    const int t0  = blockIdx.x * 64;
    const int b   = blockIdx.y;
    const int ot  = blockIdx.z;     // 0..2

    for (int idx = tid; idx < 64 * 32; idx += 256) {
        int tl = idx >> 5, k4 = idx & 31;
        float4 v = __ldg((const float4*)(Z + (size_t)(t0 + tl) * 1024 + b * 128) + k4);
        *(float4*)(Xs + tl * 132 + k4 * 4) = v;
    }
    for (int idx = tid; idx < 64 * 64; idx += 256)
        Rs[idx] = __ldg(R + (size_t)t0 * 64 + idx);
    __syncthreads();

    const int tx = tid & 31, ty = tid >> 5;
    const int oin = ot * 128 + tx * 4;
    if (oin >= 352) return;          // no further syncs below
    const int orow = b * 352 + oin;

    float accg[8][4], accf[8][4];
#pragma unroll
    for (int j = 0; j < 8; j++)
#pragma unroll
        for (int i = 0; i < 4; i++) { accg[j][i] = 0.f; accf[j][i] = 0.f; }

    const float4* Wg4 = (const float4*)Wg + (size_t)orow * 32;   // rows of 128 floats
    const float4* Wf4 = (const float4*)Wf + (size_t)orow * 32;
    for (int k4 = 0; k4 < 32; k4++) {
        float4 wg[4], wf[4];
#pragma unroll
        for (int i = 0; i < 4; i++) {
            wg[i] = __ldg(Wg4 + i * 32 + k4);
            wf[i] = __ldg(Wf4 + i * 32 + k4);
        }
#pragma unroll
        for (int j = 0; j < 8; j++) {
            float4 xv = *(const float4*)(Xs + (ty * 8 + j) * 132 + k4 * 4);
#pragma unroll
            for (int i = 0; i < 4; i++) {
                accg[j][i] = dot4(wg[i], xv, accg[j][i]);
                accf[j][i] = dot4(wf[i], xv, accf[j][i]);
            }
        }
    }

    const float4* Ag4 = (const float4*)Ag + (size_t)orow * 8;
    const float4* Af4 = (const float4*)Af + (size_t)orow * 8;
#pragma unroll
    for (int r4 = 0; r4 < 8; r4++) {
        float4 av[4], bv[4];
#pragma unroll
        for (int i = 0; i < 4; i++) {
            av[i] = __ldg(Ag4 + i * 8 + r4);
            bv[i] = __ldg(Af4 + i * 8 + r4);
        }
#pragma unroll
        for (int j = 0; j < 8; j++) {
            float4 rg = *(const float4*)(Rs + (ty * 8 + j) * 64 + r4 * 4);
            float4 rf = *(const float4*)(Rs + (ty * 8 + j) * 64 + 32 + r4 * 4);
#pragma unroll
            for (int i = 0; i < 4; i++) {
                accg[j][i] = dot4(av[i], rg, accg[j][i]);
                accf[j][i] = dot4(bv[i], rf, accf[j][i]);
            }
        }
    }

#pragma unroll
    for (int j = 0; j < 8; j++) {
        int tg = t0 + ty * 8 + j;
        float4 ov;
        float g0 = accg[j][0], g1 = accg[j][1], g2 = accg[j][2], g3 = accg[j][3];
        ov.x = g0 * sigf(g0) * accf[j][0];
        ov.y = g1 * sigf(g1) * accf[j][1];
        ov.z = g2 * sigf(g2) * accf[j][2];
        ov.w = g3 * sigf(g3) * accf[j][3];
        *(float4*)(FF + (size_t)tg * 2816 + orow) = ov;
    }
}

// ---------------------------------------------------------------------------
// k_out: per CTA = 32 tokens x block b (128 outputs). K = 352.
// out = h + blockdiag(ffp_W)@ff + ffp_A @ R
// ---------------------------------------------------------------------------
#define OUT_SMEM ((32 * 356 + 32 * 32) * 4)
__global__ __launch_bounds__(256)
void k_out(const float* __restrict__ FF, const float* __restrict__ R,
           const float* __restrict__ Wp, const float* __restrict__ Ap,
           const float* __restrict__ hin, float* __restrict__ outp) {
    extern __shared__ float sm[];
    float* Xs = sm;                 // 32 x 356 (padded)
    float* Rs = sm + 32 * 356;      // 32 x 32
    const int tid = threadIdx.x;
    const int t0  = blockIdx.x * 32;
    const int b   = blockIdx.y;

    for (int idx = tid; idx < 32 * 88; idx += 256) {
        int tl = idx / 88, k4 = idx % 88;
        float4 v = __ldg((const float4*)(FF + (size_t)(t0 + tl) * 2816 + b * 352) + k4);
        *(float4*)(Xs + tl * 356 + k4 * 4) = v;
    }
    for (int idx = tid; idx < 32 * 32; idx += 256)
        Rs[idx] = __ldg(R + (size_t)(t0 + (idx >> 5)) * 64 + (idx & 31));
    __syncthreads();

    const int tx = tid & 31, ty = tid >> 5;
    const int o = tx * 4, orow = b * 128 + o;
    float acc[4][4];
#pragma unroll
    for (int j = 0; j < 4; j++)
#pragma unroll
        for (int i = 0; i < 4; i++) acc[j][i] = 0.f;

    const float4* Wp4 = (const float4*)Wp + (size_t)orow * 88;   // rows of 352 floats
    for (int k4 = 0; k4 < 88; k4++) {
        float4 w[4];
#pragma unroll
        for (int i = 0; i < 4; i++) w[i] = __ldg(Wp4 + i * 88 + k4);
#pragma unroll
        for (int j = 0; j < 4; j++) {
            float4 xv = *(const float4*)(Xs + (ty * 4 + j) * 356 + k4 * 4);
#pragma unroll
            for (int i = 0; i < 4; i++) acc[j][i] = dot4(w[i], xv, acc[j][i]);
        }
    }

    const float4* Ap4 = (const float4*)Ap + (size_t)orow * 8;
#pragma unroll
    for (int r4 = 0; r4 < 8; r4++) {
        float4 av[4];
#pragma unroll
        for (int i = 0; i < 4; i++) av[i] = __ldg(Ap4 + i * 8 + r4);
#pragma unroll
        for (int j = 0; j < 4; j++) {
            float4 rv = *(const float4*)(Rs + (ty * 4 + j) * 32 + r4 * 4);
#pragma unroll
            for (int i = 0; i < 4; i++) acc[j][i] = dot4(av[i], rv, acc[j][i]);
        }
    }

#pragma unroll
    for (int j = 0; j < 4; j++) {
        int tg = t0 + ty * 4 + j;
        float4 hv = __ldg((const float4*)(hin + (size_t)tg * 1024 + orow));
        float4 ov = make_float4(hv.x + acc[j][0], hv.y + acc[j][1],
                                hv.z + acc[j][2], hv.w + acc[j][3]);
        *(float4*)(outp + (size_t)tg * 1024 + orow) = ov;
    }
}

// ---------------------------------------------------------------------------
// Host launcher
// ---------------------------------------------------------------------------
extern "C" void kernel_launch(void* const* d_in, const int* in_sizes, int n_in,
                              void* d_out, int out_size) {
    const float* x    = (const float*)d_in[0];
    const float* fgW  = (const float*)d_in[1];
    const float* fgA  = (const float*)d_in[2];
    const float* fgB  = (const float*)d_in[3];
    const float* guW  = (const float*)d_in[4];
    const float* guA  = (const float*)d_in[5];
    const float* guB  = (const float*)d_in[6];
    const float* ffgW = (const float*)d_in[7];
    const float* ffgA = (const float*)d_in[8];
    const float* ffgB = (const float*)d_in[9];
    const float* fffW = (const float*)d_in[10];
    const float* fffA = (const float*)d_in[11];
    const float* fffB = (const float*)d_in[12];
    const float* ffpW = (const float*)d_in[13];
    const float* ffpA = (const float*)d_in[14];
    const float* ffpB = (const float*)d_in[15];
    float* outp = (float*)d_out;

    float *H, *Z, *Rr, *FF;
    cudaGetSymbolAddress((void**)&H,  g_H);
    cudaGetSymbolAddress((void**)&Z,  g_Z);
    cudaGetSymbolAddress((void**)&Rr, g_R);
    cudaGetSymbolAddress((void**)&FF, g_FF);

    cudaFuncSetAttribute(k_iter, cudaFuncAttributeMaxDynamicSharedMemorySize, ITER_SMEM);
    cudaFuncSetAttribute(k_ff,   cudaFuncAttributeMaxDynamicSharedMemorySize, FF_SMEM);
    cudaFuncSetAttribute(k_out,  cudaFuncAttributeMaxDynamicSharedMemorySize, OUT_SMEM);

    const float* hcur = x;
    for (int it = 0; it < 4; it++) {
        k_rms<<<NTOK, 256>>>(hcur, Z);
        k_rank<64, 2048, 1024, true><<<NTOK / 64, 256>>>(Z, fgB, guB, Rr);
        k_iter<<<dim3(NTOK / 64, 8), 256, ITER_SMEM>>>(Z, Rr, fgW, guW, fgA, guA, hcur, H);
        hcur = H;
    }
    k_rms<<<NTOK, 256>>>(H, Z);
    k_rank<64, 1024, 1024, false><<<NTOK / 64, 256>>>(Z, ffgB, fffB, Rr);
    k_ff<<<dim3(NTOK / 64, 8, 3), 256, FF_SMEM>>>(Z, Rr, ffgW, fffW, ffgA, fffA, FF);
    k_rank<32, 2816, 2816, false><<<NTOK / 64, 256>>>(FF, ffpB, ffpB, Rr);
    k_out<<<dim3(NTOK / 32, 8), 256, OUT_SMEM>>>(FF, Rr, ffpW, ffpA, H, outp);
}

// round 3
// speedup vs baseline: 2.4289x; 2.4289x over previous
#include <cuda_runtime.h>
#include <cuda_bf16.h>
#include <math.h>

// ---------------------------------------------------------------------------
// IterativeBlock: h[8,2048,1024] fp32
//   4x { z = rmsnorm(h); combined = [z, shift(z)];
//        h += sigmoid(ls_fg(combined)) * ls_gu(combined) }
//   z = rmsnorm(h); ff = silu(ls_ffg(z)) * ls_fff(z); out = h + ls_ffp(ff)
//   ls(x) = blockdiag(W) x + A (B x), NUM_BLOCKS = 8
//
// All GEMMs: smem-tiled both operands, transposed [k][*] layouts, packed
// fp32x2 FMA (accumulator pairs over the token dimension).
// ---------------------------------------------------------------------------

#define NTOK 16384
#define EPSF 1.1920929e-07f

__device__ float g_H [NTOK * 1024];
__device__ float g_Z [NTOK * 1024];
__device__ float g_R [NTOK * 64];
__device__ float g_FF[NTOK * 2816];

typedef unsigned long long u64;

__device__ __forceinline__ float sigf(float x) { return 1.0f / (1.0f + __expf(-x)); }

__device__ __forceinline__ u64 pk2(float lo, float hi) {
    u64 r; asm("mov.b64 %0, {%1, %2};" : "=l"(r) : "f"(lo), "f"(hi)); return r;
}
__device__ __forceinline__ u64 dup2(float v) { return pk2(v, v); }
__device__ __forceinline__ void upk2(u64 p, float& lo, float& hi) {
    asm("mov.b64 {%0, %1}, %2;" : "=f"(lo), "=f"(hi) : "l"(p));
}
__device__ __forceinline__ void fma2(u64& d, u64 a, u64 b) {
    asm("fma.rn.f32x2 %0, %1, %2, %0;" : "+l"(d) : "l"(a), "l"(b));
}

// ---------------------------------------------------------------------------
// k_rms: one CTA per token.
// ---------------------------------------------------------------------------
__global__ __launch_bounds__(256)
void k_rms(const float* __restrict__ h, float* __restrict__ z) {
    __shared__ float ws[8];
    const int t = blockIdx.x, tid = threadIdx.x;
    float4 v = __ldg((const float4*)(h + (size_t)t * 1024) + tid);
    float s = v.x * v.x + v.y * v.y + v.z * v.z + v.w * v.w;
#pragma unroll
    for (int off = 16; off; off >>= 1) s += __shfl_xor_sync(0xffffffffu, s, off);
    if ((tid & 31) == 0) ws[tid >> 5] = s;
    __syncthreads();
    if (tid < 32) {
        float x2 = (tid < 8) ? ws[tid] : 0.0f;
#pragma unroll
        for (int off = 4; off; off >>= 1) x2 += __shfl_xor_sync(0xffffffffu, x2, off);
        if (tid == 0) ws[0] = rsqrtf(x2 * (1.0f / 1024.0f) + EPSF);
    }
    __syncthreads();
    const float inv = ws[0];
    *((float4*)(z + (size_t)t * 1024) + tid) =
        make_float4(v.x * inv, v.y * inv, v.z * inv, v.w * inv);
}

// ---------------------------------------------------------------------------
// k_rank: R[t, 0:32] = B1 @ in_t ; (NO=64: also R[t, 32:64] = B2 @ in_t)
// in_t = [Z[t], Z[t-1]] if SHIFT else src[t].
// Tile: 128 tokens x NO outs; transposed smem; fp32x2 over token pairs.
// ---------------------------------------------------------------------------
template<int NO, int KD, int SRCS, bool SHIFT>
__global__ __launch_bounds__(256)
void k_rank(const float* __restrict__ src,
            const float* __restrict__ B1, const float* __restrict__ B2,
            float* __restrict__ R) {
    constexpr int TX = NO / 4, TY = 256 / TX, TP = 128 / TY, NPJ = TP / 2;
    constexpr int BST = NO + 4;
    __shared__ float Xs[32 * 136];
    __shared__ float Bs[32 * BST];
    const int tid = threadIdx.x, t0 = blockIdx.x * 128;
    const int tx = tid % TX, ty = tid / TX;
    const int o0 = tx * 4, tl0 = ty * TP;

    u64 acc[NPJ][4];
#pragma unroll
    for (int jp = 0; jp < NPJ; jp++)
#pragma unroll
        for (int i = 0; i < 4; i++) acc[jp][i] = 0ull;

    for (int kc = 0; kc < KD; kc += 32) {
        __syncthreads();
        int roff = 0, col = kc;
        if (SHIFT && kc >= 1024) { roff = -1; col = kc - 1024; }
        for (int idx = tid; idx < 1024; idx += 256) {
            int tl = idx >> 3, k4 = idx & 7;
            float4 v = make_float4(0.f, 0.f, 0.f, 0.f);
            if (!SHIFT || roff == 0 || ((t0 + tl) & 2047) != 0)
                v = __ldg((const float4*)(src + (size_t)(t0 + tl + roff) * SRCS + col) + k4);
            Xs[(k4 * 4 + 0) * 136 + tl] = v.x;
            Xs[(k4 * 4 + 1) * 136 + tl] = v.y;
            Xs[(k4 * 4 + 2) * 136 + tl] = v.z;
            Xs[(k4 * 4 + 3) * 136 + tl] = v.w;
        }
        for (int idx = tid; idx < NO * 8; idx += 256) {
            int o = idx >> 3, k4 = idx & 7;
            const float* Bp = (o < 32) ? (B1 + (size_t)o * KD)
                                       : (B2 + (size_t)(o - 32) * KD);
            float4 v = __ldg((const float4*)(Bp + kc) + k4);
            Bs[(k4 * 4 + 0) * BST + o] = v.x;
            Bs[(k4 * 4 + 1) * BST + o] = v.y;
            Bs[(k4 * 4 + 2) * BST + o] = v.z;
            Bs[(k4 * 4 + 3) * BST + o] = v.w;
        }
        __syncthreads();
#pragma unroll
        for (int k = 0; k < 32; k++) {
            float4 b4 = *(const float4*)(Bs + k * BST + o0);
            u64 wp[4] = { dup2(b4.x), dup2(b4.y), dup2(b4.z), dup2(b4.w) };
            u64 xp[NPJ];
            {
                ulonglong2 q = *(const ulonglong2*)(Xs + k * 136 + tl0);
                xp[0] = q.x; xp[1] = q.y;
            }
            if constexpr (NPJ == 4) {
                ulonglong2 q = *(const ulonglong2*)(Xs + k * 136 + tl0 + 4);
                xp[2] = q.x; xp[3] = q.y;
            }
#pragma unroll
            for (int jp = 0; jp < NPJ; jp++)
#pragma unroll
                for (int i = 0; i < 4; i++) fma2(acc[jp][i], xp[jp], wp[i]);
        }
    }
#pragma unroll
    for (int jp = 0; jp < NPJ; jp++) {
        float lo[4], hi[4];
#pragma unroll
        for (int i = 0; i < 4; i++) upk2(acc[jp][i], lo[i], hi[i]);
        int ta = t0 + tl0 + 2 * jp;
        *(float4*)(R + (size_t)ta * 64 + o0)       = make_float4(lo[0], lo[1], lo[2], lo[3]);
        *(float4*)(R + (size_t)(ta + 1) * 64 + o0) = make_float4(hi[0], hi[1], hi[2], hi[3]);
    }
}

// ---------------------------------------------------------------------------
// k_iter: CTA = 64 tokens x blockdiag block b (128 outs, K=256).
// Both matrices (fg, gu); hout = hin + sigmoid(yg) * yu.
// smem: Xs[32x68] Wgs/Wus[32x132] Ags/Aus[32x132] RsT[64x68]  (93,696 B)
// ---------------------------------------------------------------------------
#define ITER_SMEM 93696
__global__ __launch_bounds__(256)
void k_iter(const float* __restrict__ Z, const float* __restrict__ Rg,
            const float* __restrict__ Wg, const float* __restrict__ Wu,
            const float* __restrict__ Ag, const float* __restrict__ Au,
            const float* __restrict__ hin, float* __restrict__ hout) {
    extern __shared__ float sm[];
    float* Xs  = sm;             // 32x68
    float* Wgs = sm + 2176;      // 32x132
    float* Wus = sm + 6400;
    float* Ags = sm + 10624;
    float* Aus = sm + 14848;
    float* RsT = sm + 19072;     // 64x68
    const int tid = threadIdx.x, t0 = blockIdx.x * 64, b = blockIdx.y;
    const int roff = (b < 4) ? 0 : -1, cbase = (b & 3) * 256, ob = b * 128;
    const int tx = tid & 31, ty = tid >> 5, o0 = tx * 4, tl0 = ty * 8;

    // preload A (transposed) and R (transposed) once
    for (int idx = tid; idx < 1024; idx += 256) {
        int o = idx >> 3, r4 = idx & 7;
        float4 a = __ldg((const float4*)(Ag + (size_t)(ob + o) * 32) + r4);
        Ags[(r4 * 4 + 0) * 132 + o] = a.x; Ags[(r4 * 4 + 1) * 132 + o] = a.y;
        Ags[(r4 * 4 + 2) * 132 + o] = a.z; Ags[(r4 * 4 + 3) * 132 + o] = a.w;
        float4 u = __ldg((const float4*)(Au + (size_t)(ob + o) * 32) + r4);
        Aus[(r4 * 4 + 0) * 132 + o] = u.x; Aus[(r4 * 4 + 1) * 132 + o] = u.y;
        Aus[(r4 * 4 + 2) * 132 + o] = u.z; Aus[(r4 * 4 + 3) * 132 + o] = u.w;
    }
    for (int idx = tid; idx < 1024; idx += 256) {
        int tl = idx >> 4, r4 = idx & 15;
        float4 r = __ldg((const float4*)(Rg + (size_t)(t0 + tl) * 64) + r4);
        RsT[(r4 * 4 + 0) * 68 + tl] = r.x; RsT[(r4 * 4 + 1) * 68 + tl] = r.y;
        RsT[(r4 * 4 + 2) * 68 + tl] = r.z; RsT[(r4 * 4 + 3) * 68 + tl] = r.w;
    }

    u64 ag2[4][4], au2[4][4];
#pragma unroll
    for (int jp = 0; jp < 4; jp++)
#pragma unroll
        for (int i = 0; i < 4; i++) { ag2[jp][i] = 0ull; au2[jp][i] = 0ull; }

    for (int kc = 0; kc < 256; kc += 32) {
        __syncthreads();
        for (int idx = tid; idx < 512; idx += 256) {
            int tl = idx >> 3, k4 = idx & 7;
            float4 v = make_float4(0.f, 0.f, 0.f, 0.f);
            if (roff == 0 || ((t0 + tl) & 2047) != 0)
                v = __ldg((const float4*)(Z + (size_t)(t0 + tl + roff) * 1024 + cbase + kc) + k4);
            Xs[(k4 * 4 + 0) * 68 + tl] = v.x; Xs[(k4 * 4 + 1) * 68 + tl] = v.y;
            Xs[(k4 * 4 + 2) * 68 + tl] = v.z; Xs[(k4 * 4 + 3) * 68 + tl] = v.w;
        }
        for (int idx = tid; idx < 1024; idx += 256) {
            int o = idx >> 3, k4 = idx & 7;
            float4 g = __ldg((const float4*)(Wg + (size_t)(ob + o) * 256 + kc) + k4);
            Wgs[(k4 * 4 + 0) * 132 + o] = g.x; Wgs[(k4 * 4 + 1) * 132 + o] = g.y;
            Wgs[(k4 * 4 + 2) * 132 + o] = g.z; Wgs[(k4 * 4 + 3) * 132 + o] = g.w;
            float4 u = __ldg((const float4*)(Wu + (size_t)(ob + o) * 256 + kc) + k4);
            Wus[(k4 * 4 + 0) * 132 + o] = u.x; Wus[(k4 * 4 + 1) * 132 + o] = u.y;
            Wus[(k4 * 4 + 2) * 132 + o] = u.z; Wus[(k4 * 4 + 3) * 132 + o] = u.w;
        }
        __syncthreads();
#pragma unroll
        for (int k = 0; k < 32; k++) {
            u64 xp[4];
            ulonglong2 qa = *(const ulonglong2*)(Xs + k * 68 + tl0);
            ulonglong2 qb = *(const ulonglong2*)(Xs + k * 68 + tl0 + 4);
            xp[0] = qa.x; xp[1] = qa.y; xp[2] = qb.x; xp[3] = qb.y;
            float4 g4 = *(const float4*)(Wgs + k * 132 + o0);
            float4 u4 = *(const float4*)(Wus + k * 132 + o0);
            u64 gp[4] = { dup2(g4.x), dup2(g4.y), dup2(g4.z), dup2(g4.w) };
            u64 up[4] = { dup2(u4.x), dup2(u4.y), dup2(u4.z), dup2(u4.w) };
#pragma unroll
            for (int jp = 0; jp < 4; jp++)
#pragma unroll
                for (int i = 0; i < 4; i++) {
                    fma2(ag2[jp][i], xp[jp], gp[i]);
                    fma2(au2[jp][i], xp[jp], up[i]);
                }
        }
    }

    // low-rank term: A @ R
#pragma unroll 4
    for (int r = 0; r < 32; r++) {
        float4 a4 = *(const float4*)(Ags + r * 132 + o0);
        float4 b4 = *(const float4*)(Aus + r * 132 + o0);
        u64 ap[4] = { dup2(a4.x), dup2(a4.y), dup2(a4.z), dup2(a4.w) };
        u64 bp[4] = { dup2(b4.x), dup2(b4.y), dup2(b4.z), dup2(b4.w) };
        u64 rgp[4], rup[4];
        ulonglong2 q1 = *(const ulonglong2*)(RsT + r * 68 + tl0);
        ulonglong2 q2 = *(const ulonglong2*)(RsT + r * 68 + tl0 + 4);
        rgp[0] = q1.x; rgp[1] = q1.y; rgp[2] = q2.x; rgp[3] = q2.y;
        ulonglong2 q3 = *(const ulonglong2*)(RsT + (32 + r) * 68 + tl0);
        ulonglong2 q4 = *(const ulonglong2*)(RsT + (32 + r) * 68 + tl0 + 4);
        rup[0] = q3.x; rup[1] = q3.y; rup[2] = q4.x; rup[3] = q4.y;
#pragma unroll
        for (int jp = 0; jp < 4; jp++)
#pragma unroll
            for (int i = 0; i < 4; i++) {
                fma2(ag2[jp][i], rgp[jp], ap[i]);
                fma2(au2[jp][i], rup[jp], bp[i]);
            }
    }

#pragma unroll
    for (int jp = 0; jp < 4; jp++) {
        float gl[4], gh[4], ul[4], uh[4];
#pragma unroll
        for (int i = 0; i < 4; i++) { upk2(ag2[jp][i], gl[i], gh[i]); upk2(au2[jp][i], ul[i], uh[i]); }
        int ta = t0 + tl0 + 2 * jp;
        float4 h0 = __ldg((const float4*)(hin + (size_t)ta * 1024 + ob + o0));
        *(float4*)(hout + (size_t)ta * 1024 + ob + o0) = make_float4(
            fmaf(sigf(gl[0]), ul[0], h0.x), fmaf(sigf(gl[1]), ul[1], h0.y),
            fmaf(sigf(gl[2]), ul[2], h0.z), fmaf(sigf(gl[3]), ul[3], h0.w));
        float4 h1 = __ldg((const float4*)(hin + (size_t)(ta + 1) * 1024 + ob + o0));
        *(float4*)(hout + (size_t)(ta + 1) * 1024 + ob + o0) = make_float4(
            fmaf(sigf(gh[0]), uh[0], h1.x), fmaf(sigf(gh[1]), uh[1], h1.y),
            fmaf(sigf(gh[2]), uh[2], h1.z), fmaf(sigf(gh[3]), uh[3], h1.w));
    }
}

// ---------------------------------------------------------------------------
// k_ff: CTA = 64 tokens x (block b, out-tile ot). K=128, outs {128,128,96}.
// FF = silu(ls_ffg(z)) * ls_fff(z)
// ---------------------------------------------------------------------------
#define FF_SMEM 93696
__global__ __launch_bounds__(256)
void k_ff(const float* __restrict__ Z, const float* __restrict__ Rg,
          const float* __restrict__ Wg, const float* __restrict__ Wf,
          const float* __restrict__ Ag, const float* __restrict__ Af,
          float* __restrict__ FF) {
    extern __shared__ float sm[];
    float* Xs  = sm;
    float* Wgs = sm + 2176;
    float* Wfs = sm + 6400;
    float* Ags = sm + 10624;
    float* Afs = sm + 14848;
    float* RsT = sm + 19072;
    const int tid = threadIdx.x, t0 = blockIdx.x * 64, b = blockIdx.y, ot = blockIdx.z;
    const int nav = (ot == 2) ? 96 : 128;
    const int obase = b * 352 + ot * 128;
    const int tx = tid & 31, ty = tid >> 5, o0 = tx * 4, tl0 = ty * 8;
    const bool active = (o0 < nav);

    for (int idx = tid; idx < 1024; idx += 256) {
        int o = idx >> 3, r4 = idx & 7;
        if (o < nav) {
            float4 a = __ldg((const float4*)(Ag + (size_t)(obase + o) * 32) + r4);
            Ags[(r4 * 4 + 0) * 132 + o] = a.x; Ags[(r4 * 4 + 1) * 132 + o] = a.y;
            Ags[(r4 * 4 + 2) * 132 + o] = a.z; Ags[(r4 * 4 + 3) * 132 + o] = a.w;
            float4 f = __ldg((const float4*)(Af + (size_t)(obase + o) * 32) + r4);
            Afs[(r4 * 4 + 0) * 132 + o] = f.x; Afs[(r4 * 4 + 1) * 132 + o] = f.y;
            Afs[(r4 * 4 + 2) * 132 + o] = f.z; Afs[(r4 * 4 + 3) * 132 + o] = f.w;
        }
    }
    for (int idx = tid; idx < 1024; idx += 256) {
        int tl = idx >> 4, r4 = idx & 15;
        float4 r = __ldg((const float4*)(Rg + (size_t)(t0 + tl) * 64) + r4);
        RsT[(r4 * 4 + 0) * 68 + tl] = r.x; RsT[(r4 * 4 + 1) * 68 + tl] = r.y;
        RsT[(r4 * 4 + 2) * 68 + tl] = r.z; RsT[(r4 * 4 + 3) * 68 + tl] = r.w;
    }

    u64 ag2[4][4], af2[4][4];
#pragma unroll
    for (int jp = 0; jp < 4; jp++)
#pragma unroll
        for (int i = 0; i < 4; i++) { ag2[jp][i] = 0ull; af2[jp][i] = 0ull; }

    for (int kc = 0; kc < 128; kc += 32) {
        __syncthreads();
        for (int idx = tid; idx < 512; idx += 256) {
            int tl = idx >> 3, k4 = idx & 7;
            float4 v = __ldg((const float4*)(Z + (size_t)(t0 + tl) * 1024 + b * 128 + kc) + k4);
            Xs[(k4 * 4 + 0) * 68 + tl] = v.x; Xs[(k4 * 4 + 1) * 68 + tl] = v.y;
            Xs[(k4 * 4 + 2) * 68 + tl] = v.z; Xs[(k4 * 4 + 3) * 68 + tl] = v.w;
        }
        for (int idx = tid; idx < 1024; idx += 256) {
            int o = idx >> 3, k4 = idx & 7;
            if (o < nav) {
                float4 g = __ldg((const float4*)(Wg + (size_t)(obase + o) * 128 + kc) + k4);
                Wgs[(k4 * 4 + 0) * 132 + o] = g.x; Wgs[(k4 * 4 + 1) * 132 + o] = g.y;
                Wgs[(k4 * 4 + 2) * 132 + o] = g.z; Wgs[(k4 * 4 + 3) * 132 + o] = g.w;
                float4 f = __ldg((const float4*)(Wf + (size_t)(obase + o) * 128 + kc) + k4);
                Wfs[(k4 * 4 + 0) * 132 + o] = f.x; Wfs[(k4 * 4 + 1) * 132 + o] = f.y;
                Wfs[(k4 * 4 + 2) * 132 + o] = f.z; Wfs[(k4 * 4 + 3) * 132 + o] = f.w;
            }
        }
        __syncthreads();
        if (active) {
#pragma unroll
            for (int k = 0; k < 32; k++) {
                u64 xp[4];
                ulonglong2 qa = *(const ulonglong2*)(Xs + k * 68 + tl0);
                ulonglong2 qb = *(const ulonglong2*)(Xs + k * 68 + tl0 + 4);
                xp[0] = qa.x; xp[1] = qa.y; xp[2] = qb.x; xp[3] = qb.y;
                float4 g4 = *(const float4*)(Wgs + k * 132 + o0);
                float4 f4 = *(const float4*)(Wfs + k * 132 + o0);
                u64 gp[4] = { dup2(g4.x), dup2(g4.y), dup2(g4.z), dup2(g4.w) };
                u64 fp[4] = { dup2(f4.x), dup2(f4.y), dup2(f4.z), dup2(f4.w) };
#pragma unroll
                for (int jp = 0; jp < 4; jp++)
#pragma unroll
                    for (int i = 0; i < 4; i++) {
                        fma2(ag2[jp][i], xp[jp], gp[i]);
                        fma2(af2[jp][i], xp[jp], fp[i]);
                    }
            }
        }
    }

    if (active) {
#pragma unroll 4
        for (int r = 0; r < 32; r++) {
            float4 a4 = *(const float4*)(Ags + r * 132 + o0);
            float4 b4 = *(const float4*)(Afs + r * 132 + o0);
            u64 ap[4] = { dup2(a4.x), dup2(a4.y), dup2(a4.z), dup2(a4.w) };
            u64 bp[4] = { dup2(b4.x), dup2(b4.y), dup2(b4.z), dup2(b4.w) };
            u64 rgp[4], rfp[4];
            ulonglong2 q1 = *(const ulonglong2*)(RsT + r * 68 + tl0);
            ulonglong2 q2 = *(const ulonglong2*)(RsT + r * 68 + tl0 + 4);
            rgp[0] = q1.x; rgp[1] = q1.y; rgp[2] = q2.x; rgp[3] = q2.y;
            ulonglong2 q3 = *(const ulonglong2*)(RsT + (32 + r) * 68 + tl0);
            ulonglong2 q4 = *(const ulonglong2*)(RsT + (32 + r) * 68 + tl0 + 4);
            rfp[0] = q3.x; rfp[1] = q3.y; rfp[2] = q4.x; rfp[3] = q4.y;
#pragma unroll
            for (int jp = 0; jp < 4; jp++)
#pragma unroll
                for (int i = 0; i < 4; i++) {
                    fma2(ag2[jp][i], rgp[jp], ap[i]);
                    fma2(af2[jp][i], rfp[jp], bp[i]);
                }
        }
#pragma unroll
        for (int jp = 0; jp < 4; jp++) {
            float gl[4], gh[4], fl[4], fh[4];
#pragma unroll
            for (int i = 0; i < 4; i++) { upk2(ag2[jp][i], gl[i], gh[i]); upk2(af2[jp][i], fl[i], fh[i]); }
            int ta = t0 + tl0 + 2 * jp;
            *(float4*)(FF + (size_t)ta * 2816 + obase + o0) = make_float4(
                gl[0] * sigf(gl[0]) * fl[0], gl[1] * sigf(gl[1]) * fl[1],
                gl[2] * sigf(gl[2]) * fl[2], gl[3] * sigf(gl[3]) * fl[3]);
            *(float4*)(FF + (size_t)(ta + 1) * 2816 + obase + o0) = make_float4(
                gh[0] * sigf(gh[0]) * fh[0], gh[1] * sigf(gh[1]) * fh[1],
                gh[2] * sigf(gh[2]) * fh[2], gh[3] * sigf(gh[3]) * fh[3]);
        }
    }
}

// ---------------------------------------------------------------------------
// k_out: CTA = 64 tokens x block b (128 outs, K=352).
// out = h + blockdiag(ffp_W)@ff + ffp_A @ R
// ---------------------------------------------------------------------------
#define OUT_SMEM 51200
__global__ __launch_bounds__(256)
void k_out(const float* __restrict__ FF, const float* __restrict__ Rg,
           const float* __restrict__ Wp, const float* __restrict__ Ap,
           const float* __restrict__ hin, float* __restrict__ outp) {
    extern __shared__ float sm[];
    float* Xs  = sm;             // 32x68
    float* Ws  = sm + 2176;      // 32x132
    float* As  = sm + 6400;      // 32x132
    float* RsT = sm + 10624;     // 32x68
    const int tid = threadIdx.x, t0 = blockIdx.x * 64, b = blockIdx.y;
    const int ob = b * 128;
    const int tx = tid & 31, ty = tid >> 5, o0 = tx * 4, tl0 = ty * 8;

    for (int idx = tid; idx < 1024; idx += 256) {
        int o = idx >> 3, r4 = idx & 7;
        float4 a = __ldg((const float4*)(Ap + (size_t)(ob + o) * 32) + r4);
        As[(r4 * 4 + 0) * 132 + o] = a.x; As[(r4 * 4 + 1) * 132 + o] = a.y;
        As[(r4 * 4 + 2) * 132 + o] = a.z; As[(r4 * 4 + 3) * 132 + o] = a.w;
    }
    for (int idx = tid; idx < 512; idx += 256) {
        int tl = idx >> 3, r4 = idx & 7;
        float4 r = __ldg((const float4*)(Rg + (size_t)(t0 + tl) * 64) + r4);
        RsT[(r4 * 4 + 0) * 68 + tl] = r.x; RsT[(r4 * 4 + 1) * 68 + tl] = r.y;
        RsT[(r4 * 4 + 2) * 68 + tl] = r.z; RsT[(r4 * 4 + 3) * 68 + tl] = r.w;
    }

    u64 ac2[4][4];
#pragma unroll
    for (int jp = 0; jp < 4; jp++)
#pragma unroll
        for (int i = 0; i < 4; i++) ac2[jp][i] = 0ull;

    for (int kc = 0; kc < 352; kc += 32) {
        __syncthreads();
        for (int idx = tid; idx < 512; idx += 256) {
            int tl = idx >> 3, k4 = idx & 7;
            float4 v = __ldg((const float4*)(FF + (size_t)(t0 + tl) * 2816 + b * 352 + kc) + k4);
            Xs[(k4 * 4 + 0) * 68 + tl] = v.x; Xs[(k4 * 4 + 1) * 68 + tl] = v.y;
            Xs[(k4 * 4 + 2) * 68 + tl] = v.z; Xs[(k4 * 4 + 3) * 68 + tl] = v.w;
        }
        for (int idx = tid; idx < 1024; idx += 256) {
            int o = idx >> 3, k4 = idx & 7;
            float4 w = __ldg((const float4*)(Wp + (size_t)(ob + o) * 352 + kc) + k4);
            Ws[(k4 * 4 + 0) * 132 + o] = w.x; Ws[(k4 * 4 + 1) * 132 + o] = w.y;
            Ws[(k4 * 4 + 2) * 132 + o] = w.z; Ws[(k4 * 4 + 3) * 132 + o] = w.w;
        }
        __syncthreads();
#pragma unroll
        for (int k = 0; k < 32; k++) {
            u64 xp[4];
            ulonglong2 qa = *(const ulonglong2*)(Xs + k * 68 + tl0);
            ulonglong2 qb = *(const ulonglong2*)(Xs + k * 68 + tl0 + 4);
            xp[0] = qa.x; xp[1] = qa.y; xp[2] = qb.x; xp[3] = qb.y;
            float4 w4 = *(const float4*)(Ws + k * 132 + o0);
            u64 wp[4] = { dup2(w4.x), dup2(w4.y), dup2(w4.z), dup2(w4.w) };
#pragma unroll
            for (int jp = 0; jp < 4; jp++)
#pragma unroll
                for (int i = 0; i < 4; i++) fma2(ac2[jp][i], xp[jp], wp[i]);
        }
    }

#pragma unroll 4
    for (int r = 0; r < 32; r++) {
        float4 a4 = *(const float4*)(As + r * 132 + o0);
        u64 ap[4] = { dup2(a4.x), dup2(a4.y), dup2(a4.z), dup2(a4.w) };
        u64 rp[4];
        ulonglong2 q1 = *(const ulonglong2*)(RsT + r * 68 + tl0);
        ulonglong2 q2 = *(const ulonglong2*)(RsT + r * 68 + tl0 + 4);
        rp[0] = q1.x; rp[1] = q1.y; rp[2] = q2.x; rp[3] = q2.y;
#pragma unroll
        for (int jp = 0; jp < 4; jp++)
#pragma unroll
            for (int i = 0; i < 4; i++) fma2(ac2[jp][i], rp[jp], ap[i]);
    }

#pragma unroll
    for (int jp = 0; jp < 4; jp++) {
        float lo[4], hi[4];
#pragma unroll
        for (int i = 0; i < 4; i++) upk2(ac2[jp][i], lo[i], hi[i]);
        int ta = t0 + tl0 + 2 * jp;
        float4 h0 = __ldg((const float4*)(hin + (size_t)ta * 1024 + ob + o0));
        *(float4*)(outp + (size_t)ta * 1024 + ob + o0) =
            make_float4(h0.x + lo[0], h0.y + lo[1], h0.z + lo[2], h0.w + lo[3]);
        float4 h1 = __ldg((const float4*)(hin + (size_t)(ta + 1) * 1024 + ob + o0));
        *(float4*)(outp + (size_t)(ta + 1) * 1024 + ob + o0) =
            make_float4(h1.x + hi[0], h1.y + hi[1], h1.z + hi[2], h1.w + hi[3]);
    }
}

// ---------------------------------------------------------------------------
// Host launcher
// ---------------------------------------------------------------------------
extern "C" void kernel_launch(void* const* d_in, const int* in_sizes, int n_in,
                              void* d_out, int out_size) {
    const float* x    = (const float*)d_in[0];
    const float* fgW  = (const float*)d_in[1];
    const float* fgA  = (const float*)d_in[2];
    const float* fgB  = (const float*)d_in[3];
    const float* guW  = (const float*)d_in[4];
    const float* guA  = (const float*)d_in[5];
    const float* guB  = (const float*)d_in[6];
    const float* ffgW = (const float*)d_in[7];
    const float* ffgA = (const float*)d_in[8];
    const float* ffgB = (const float*)d_in[9];
    const float* fffW = (const float*)d_in[10];
    const float* fffA = (const float*)d_in[11];
    const float* fffB = (const float*)d_in[12];
    const float* ffpW = (const float*)d_in[13];
    const float* ffpA = (const float*)d_in[14];
    const float* ffpB = (const float*)d_in[15];
    float* outp = (float*)d_out;

    float *H, *Z, *Rr, *FF;
    cudaGetSymbolAddress((void**)&H,  g_H);
    cudaGetSymbolAddress((void**)&Z,  g_Z);
    cudaGetSymbolAddress((void**)&Rr, g_R);
    cudaGetSymbolAddress((void**)&FF, g_FF);

    cudaFuncSetAttribute(k_iter, cudaFuncAttributeMaxDynamicSharedMemorySize, ITER_SMEM);
    cudaFuncSetAttribute(k_ff,   cudaFuncAttributeMaxDynamicSharedMemorySize, FF_SMEM);
    cudaFuncSetAttribute(k_out,  cudaFuncAttributeMaxDynamicSharedMemorySize, OUT_SMEM);

    const float* hcur = x;
    for (int it = 0; it < 4; it++) {
        k_rms<<<NTOK, 256>>>(hcur, Z);
        k_rank<64, 2048, 1024, true><<<NTOK / 128, 256>>>(Z, fgB, guB, Rr);
        k_iter<<<dim3(NTOK / 64, 8), 256, ITER_SMEM>>>(Z, Rr, fgW, guW, fgA, guA, hcur, H);
        hcur = H;
    }
    k_rms<<<NTOK, 256>>>(H, Z);
    k_rank<64, 1024, 1024, false><<<NTOK / 128, 256>>>(Z, ffgB, fffB, Rr);
    k_ff<<<dim3(NTOK / 64, 8, 3), 256, FF_SMEM>>>(Z, Rr, ffgW, fffW, ffgA, fffA, FF);
    k_rank<32, 2816, 2816, false><<<NTOK / 128, 256>>>(FF, ffpB, ffpB, Rr);
    k_out<<<dim3(NTOK / 64, 8), 256, OUT_SMEM>>>(FF, Rr, ffpW, ffpA, H, outp);
}

// round 5
// speedup vs baseline: 3.0076x; 1.2383x over previous
#include <cuda_runtime.h>
#include <cuda_bf16.h>
#include <math.h>
#include <stdint.h>

// ---------------------------------------------------------------------------
// IterativeBlock on GB300, compute_103-safe: dense GEMMs via warp-level
// mma.sync tf32 (sm_80 baseline PTX -> legacy tensor path on sm_103),
// rank-32 projections + rmsnorm on scalar fp32/fp32x2 pipes.
//
//   4x { z = rmsnorm(h); combined = [z, shift(z)];
//        h += sigmoid(ls_fg(combined)) * ls_gu(combined) }
//   z = rmsnorm(h); ff = silu(ls_ffg(z)) * ls_fff(z); out = h + ls_ffp(ff)
//   ls(x) = blockdiag(W) x + A (B x), NUM_BLOCKS = 8
// ---------------------------------------------------------------------------

#define NTOK 16384
#define EPSF 1.1920929e-07f

__device__ float g_H [NTOK * 1024];
__device__ float g_Z [NTOK * 1024];
__device__ float g_R [NTOK * 64];
__device__ float g_FF[NTOK * 2816];

typedef unsigned long long u64;

__device__ __forceinline__ float sigf(float x) { return 1.0f / (1.0f + __expf(-x)); }

__device__ __forceinline__ u64 pk2(float lo, float hi) {
    u64 r; asm("mov.b64 %0, {%1, %2};" : "=l"(r) : "f"(lo), "f"(hi)); return r;
}
__device__ __forceinline__ u64 dup2(float v) { return pk2(v, v); }
__device__ __forceinline__ void upk2(u64 p, float& lo, float& hi) {
    asm("mov.b64 {%0, %1}, %2;" : "=f"(lo), "=f"(hi) : "l"(p));
}
__device__ __forceinline__ void fma2(u64& d, u64 a, u64 b) {
    asm("fma.rn.f32x2 %0, %1, %2, %0;" : "+l"(d) : "l"(a), "l"(b));
}

// ---------------- warp MMA helpers (sm_80 baseline PTX) ----------------
__device__ __forceinline__ uint32_t cvt_tf32(float f) {
    uint32_t r; asm("cvt.rna.tf32.f32 %0, %1;" : "=r"(r) : "f"(f)); return r;
}
__device__ __forceinline__ float4 cvt4(float4 v) {
    return make_float4(__uint_as_float(cvt_tf32(v.x)), __uint_as_float(cvt_tf32(v.y)),
                       __uint_as_float(cvt_tf32(v.z)), __uint_as_float(cvt_tf32(v.w)));
}
__device__ __forceinline__ void mma168(float* c, const uint32_t* a, const uint32_t* b) {
    asm volatile(
        "mma.sync.aligned.m16n8k8.row.col.f32.tf32.tf32.f32 "
        "{%0,%1,%2,%3}, {%4,%5,%6,%7}, {%8,%9}, {%0,%1,%2,%3};"
        : "+f"(c[0]), "+f"(c[1]), "+f"(c[2]), "+f"(c[3])
        : "r"(a[0]), "r"(a[1]), "r"(a[2]), "r"(a[3]), "r"(b[0]), "r"(b[1]));
}

// ---------------------------------------------------------------------------
// k_rms: one CTA per token.
// ---------------------------------------------------------------------------
__global__ __launch_bounds__(256)
void k_rms(const float* __restrict__ h, float* __restrict__ z) {
    __shared__ float ws[8];
    const int t = blockIdx.x, tid = threadIdx.x;
    float4 v = __ldg((const float4*)(h + (size_t)t * 1024) + tid);
    float s = v.x * v.x + v.y * v.y + v.z * v.z + v.w * v.w;
#pragma unroll
    for (int off = 16; off; off >>= 1) s += __shfl_xor_sync(0xffffffffu, s, off);
    if ((tid & 31) == 0) ws[tid >> 5] = s;
    __syncthreads();
    if (tid < 32) {
        float x2 = (tid < 8) ? ws[tid] : 0.0f;
#pragma unroll
        for (int off = 4; off; off >>= 1) x2 += __shfl_xor_sync(0xffffffffu, x2, off);
        if (tid == 0) ws[0] = rsqrtf(x2 * (1.0f / 1024.0f) + EPSF);
    }
    __syncthreads();
    const float inv = ws[0];
    *((float4*)(z + (size_t)t * 1024) + tid) =
        make_float4(v.x * inv, v.y * inv, v.z * inv, v.w * inv);
}

// ---------------------------------------------------------------------------
// k_rank (fp32x2): R[t,0:32]=B1@in_t ; (NO=64: R[t,32:64]=B2@in_t)
// ---------------------------------------------------------------------------
template<int NO, int KD, int SRCS, bool SHIFT>
__global__ __launch_bounds__(256)
void k_rank(const float* __restrict__ src,
            const float* __restrict__ B1, const float* __restrict__ B2,
            float* __restrict__ R) {
    constexpr int TX = NO / 4, TY = 256 / TX, TP = 128 / TY, NPJ = TP / 2;
    constexpr int BST = NO + 4;
    __shared__ float Xs[32 * 136];
    __shared__ float Bs[32 * BST];
    const int tid = threadIdx.x, t0 = blockIdx.x * 128;
    const int tx = tid % TX, ty = tid / TX;
    const int o0 = tx * 4, tl0 = ty * TP;

    u64 acc[NPJ][4];
#pragma unroll
    for (int jp = 0; jp < NPJ; jp++)
#pragma unroll
        for (int i = 0; i < 4; i++) acc[jp][i] = 0ull;

    for (int kc = 0; kc < KD; kc += 32) {
        __syncthreads();
        int roff = 0, col = kc;
        if (SHIFT && kc >= 1024) { roff = -1; col = kc - 1024; }
        for (int idx = tid; idx < 1024; idx += 256) {
            int tl = idx >> 3, k4 = idx & 7;
            float4 v = make_float4(0.f, 0.f, 0.f, 0.f);
            if (!SHIFT || roff == 0 || ((t0 + tl) & 2047) != 0)
                v = __ldg((const float4*)(src + (size_t)(t0 + tl + roff) * SRCS + col) + k4);
            Xs[(k4 * 4 + 0) * 136 + tl] = v.x;
            Xs[(k4 * 4 + 1) * 136 + tl] = v.y;
            Xs[(k4 * 4 + 2) * 136 + tl] = v.z;
            Xs[(k4 * 4 + 3) * 136 + tl] = v.w;
        }
        for (int idx = tid; idx < NO * 8; idx += 256) {
            int o = idx >> 3, k4 = idx & 7;
            const float* Bp = (o < 32) ? (B1 + (size_t)o * KD)
                                       : (B2 + (size_t)(o - 32) * KD);
            float4 v = __ldg((const float4*)(Bp + kc) + k4);
            Bs[(k4 * 4 + 0) * BST + o] = v.x;
            Bs[(k4 * 4 + 1) * BST + o] = v.y;
            Bs[(k4 * 4 + 2) * BST + o] = v.z;
            Bs[(k4 * 4 + 3) * BST + o] = v.w;
        }
        __syncthreads();
#pragma unroll
        for (int k = 0; k < 32; k++) {
            float4 b4 = *(const float4*)(Bs + k * BST + o0);
            u64 wp[4] = { dup2(b4.x), dup2(b4.y), dup2(b4.z), dup2(b4.w) };
            u64 xp[NPJ];
            {
                ulonglong2 q = *(const ulonglong2*)(Xs + k * 136 + tl0);
                xp[0] = q.x; xp[1] = q.y;
            }
            if constexpr (NPJ == 4) {
                ulonglong2 q = *(const ulonglong2*)(Xs + k * 136 + tl0 + 4);
                xp[2] = q.x; xp[3] = q.y;
            }
#pragma unroll
            for (int jp = 0; jp < NPJ; jp++)
#pragma unroll
                for (int i = 0; i < 4; i++) fma2(acc[jp][i], xp[jp], wp[i]);
        }
    }
#pragma unroll
    for (int jp = 0; jp < NPJ; jp++) {
        float lo[4], hi[4];
#pragma unroll
        for (int i = 0; i < 4; i++) upk2(acc[jp][i], lo[i], hi[i]);
        int ta = t0 + tl0 + 2 * jp;
        *(float4*)(R + (size_t)ta * 64 + o0)       = make_float4(lo[0], lo[1], lo[2], lo[3]);
        *(float4*)(R + (size_t)(ta + 1) * 64 + o0) = make_float4(hi[0], hi[1], hi[2], hi[3]);
    }
}

// ---------------------------------------------------------------------------
// Fragment-layout smem staging (shared by the MMA kernels).
// A stage: [k8:4][mi:4][reg:4][lane:32]  (2048 floats, 8 KB)
// B stage: [k8:4][ni:NI][reg:2][lane:32] (NI*256 floats)
// XOR swizzle s=(k8*2+q)*4 on the lane index keeps both STS.128 staging and
// LDS.32 fragment reads bank-conflict-free.
// ---------------------------------------------------------------------------
__device__ __forceinline__ void stageA4(float* As, int row, int q4, float4 v) {
    int k8 = q4 >> 1, q = q4 & 1;
    int rr = row & 15, mi = row >> 4;
    int reg = ((rr >> 3) & 1) + 2 * q;
    int tb = ((rr & 7) * 4) ^ ((k8 * 2 + q) * 4);
    *(float4*)(As + ((k8 * 4 + mi) * 4 + reg) * 32 + tb) = cvt4(v);
}
template<int NI>
__device__ __forceinline__ void stageB4(float* Bs, int n, int q4, float4 v) {
    int k8 = q4 >> 1, rq = q4 & 1;
    int ni = n >> 3;
    int tb = ((n & 7) * 4) ^ ((k8 * 2 + rq) * 4);
    *(float4*)(Bs + ((k8 * NI + ni) * 2 + rq) * 32 + tb) = cvt4(v);
}
__device__ __forceinline__ void ldfragA(uint32_t* a, const float* As, int k8, int mi, int lane) {
#pragma unroll
    for (int r = 0; r < 4; r++) {
        int s = (k8 * 2 + (r >> 1)) * 4;
        a[r] = __float_as_uint(As[((k8 * 4 + mi) * 4 + r) * 32 + (lane ^ s)]);
    }
}
template<int NI>
__device__ __forceinline__ void ldfragB(uint32_t* b, const float* Bs, int k8, int ni, int lane) {
#pragma unroll
    for (int r = 0; r < 2; r++) {
        int s = (k8 * 2 + r) * 4;
        b[r] = __float_as_uint(Bs[((k8 * NI + ni) * 2 + r) * 32 + (lane ^ s)]);
    }
}

// ---------------------------------------------------------------------------
// k_iter_m: CTA = 64 tokens x block b. Fused N=256 (rows n=2*o+m: m=0 fg,
// m=1 gu), K=320 = [Z_b slice (256) | Rg(32) | Ru(32)].
// Epilogue in registers: h += sigmoid(g) * u.
// smem: A 8K x2 + B 32K x2 = 81920 B
// ---------------------------------------------------------------------------
#define ITER_SMEM 81920
__global__ __launch_bounds__(256, 2)
void k_iter_m(const float* __restrict__ Z, const float* __restrict__ Rg,
              const float* __restrict__ Wg, const float* __restrict__ Wu,
              const float* __restrict__ Ag, const float* __restrict__ Au,
              const float* __restrict__ hin, float* __restrict__ hout) {
    extern __shared__ float sm[];
    float* Abuf[2] = { sm, sm + 2048 };
    float* Bbuf[2] = { sm + 4096, sm + 12288 };
    const int tid = threadIdx.x, lane = tid & 31, wid = tid >> 5;
    const int wm = wid >> 2, wn = wid & 3;
    const int t0 = blockIdx.x * 64, b = blockIdx.y;
    const int roff = (b < 4) ? 0 : -1, cbase = (b & 3) * 256, ob = b * 128;

    float acc[2][8][4];
#pragma unroll
    for (int i = 0; i < 2; i++)
#pragma unroll
        for (int j = 0; j < 8; j++)
#pragma unroll
            for (int k = 0; k < 4; k++) acc[i][j][k] = 0.0f;

    auto stage = [&](int c, int buf) {
        float* As = Abuf[buf];
        float* Bs = Bbuf[buf];
#pragma unroll
        for (int i = 0; i < 2; i++) {
            int idx = tid + i * 256;                  // 512 float4s
            int row = idx >> 3, q4 = idx & 7;
            int tok = t0 + row;
            float4 v = make_float4(0.f, 0.f, 0.f, 0.f);
            if (c < 8) {
                if (roff == 0 || (tok & 2047) != 0)
                    v = __ldg((const float4*)(Z + (size_t)(tok + roff) * 1024 + cbase + c * 32) + q4);
            } else {
                v = __ldg((const float4*)(Rg + (size_t)tok * 64 + (c == 8 ? 0 : 32)) + q4);
            }
            stageA4(As, row, q4, v);
        }
#pragma unroll
        for (int i = 0; i < 8; i++) {
            int idx = tid + i * 256;                  // 2048 float4s
            int n = idx >> 3, q4 = idx & 7;
            int o = n >> 1, m = n & 1;
            float4 v = make_float4(0.f, 0.f, 0.f, 0.f);
            if (c < 8) {
                v = __ldg((const float4*)((m ? Wu : Wg) + (size_t)(ob + o) * 256 + c * 32) + q4);
            } else if (c == 8) {
                if (!m) v = __ldg((const float4*)(Ag + (size_t)(ob + o) * 32) + q4);
            } else {
                if (m) v = __ldg((const float4*)(Au + (size_t)(ob + o) * 32) + q4);
            }
            stageB4<32>(Bs, n, q4, v);
        }
    };
    auto compute = [&](int buf) {
        const float* As = Abuf[buf];
        const float* Bs = Bbuf[buf];
#pragma unroll
        for (int k8 = 0; k8 < 4; k8++) {
            uint32_t a[2][4], bf[8][2];
#pragma unroll
            for (int mi2 = 0; mi2 < 2; mi2++) ldfragA(a[mi2], As, k8, wm * 2 + mi2, lane);
#pragma unroll
            for (int ni2 = 0; ni2 < 8; ni2++) ldfragB<32>(bf[ni2], Bs, k8, wn * 8 + ni2, lane);
#pragma unroll
            for (int mi2 = 0; mi2 < 2; mi2++)
#pragma unroll
                for (int ni2 = 0; ni2 < 8; ni2++) mma168(acc[mi2][ni2], a[mi2], bf[ni2]);
        }
    };

    stage(0, 0);
    __syncthreads();
    for (int c = 0; c < 10; c++) {
        int buf = c & 1;
        if (c < 9) stage(c + 1, buf ^ 1);
        compute(buf);
        __syncthreads();
    }

#pragma unroll
    for (int mi2 = 0; mi2 < 2; mi2++)
#pragma unroll
        for (int ni2 = 0; ni2 < 8; ni2++) {
            int r0 = t0 + wm * 32 + mi2 * 16 + (lane >> 2);
            int o  = ob + wn * 32 + ni2 * 4 + (lane & 3);
            float g0 = acc[mi2][ni2][0], u0 = acc[mi2][ni2][1];
            hout[(size_t)r0 * 1024 + o] = hin[(size_t)r0 * 1024 + o] + sigf(g0) * u0;
            int r1 = r0 + 8;
            float g1 = acc[mi2][ni2][2], u1 = acc[mi2][ni2][3];
            hout[(size_t)r1 * 1024 + o] = hin[(size_t)r1 * 1024 + o] + sigf(g1) * u1;
        }
}

// ---------------------------------------------------------------------------
// k_ff_m: CTA = 64 tokens x block b x slice ot (outs {128,128,96}).
// Fused N=256 (n=2*oo+m: m=0 ffg, m=1 fff), K=192 = [Z_b(128)|Rg(32)|Rf(32)].
// Epilogue: FF = silu(g) * f.
// ---------------------------------------------------------------------------
__global__ __launch_bounds__(256, 2)
void k_ff_m(const float* __restrict__ Z, const float* __restrict__ Rg,
            const float* __restrict__ Wg, const float* __restrict__ Wf,
            const float* __restrict__ Ag, const float* __restrict__ Af,
            float* __restrict__ FF) {
    extern __shared__ float sm[];
    float* Abuf[2] = { sm, sm + 2048 };
    float* Bbuf[2] = { sm + 4096, sm + 12288 };
    const int tid = threadIdx.x, lane = tid & 31, wid = tid >> 5;
    const int wm = wid >> 2, wn = wid & 3;
    const int t0 = blockIdx.x * 64, b = blockIdx.y, ot = blockIdx.z;
    const int nav = (ot == 2) ? 96 : 128;
    const int obase = b * 352 + ot * 128;

    float acc[2][8][4];
#pragma unroll
    for (int i = 0; i < 2; i++)
#pragma unroll
        for (int j = 0; j < 8; j++)
#pragma unroll
            for (int k = 0; k < 4; k++) acc[i][j][k] = 0.0f;

    auto stage = [&](int c, int buf) {
        float* As = Abuf[buf];
        float* Bs = Bbuf[buf];
#pragma unroll
        for (int i = 0; i < 2; i++) {
            int idx = tid + i * 256;
            int row = idx >> 3, q4 = idx & 7;
            int tok = t0 + row;
            float4 v;
            if (c < 4)
                v = __ldg((const float4*)(Z + (size_t)tok * 1024 + b * 128 + c * 32) + q4);
            else
                v = __ldg((const float4*)(Rg + (size_t)tok * 64 + (c == 4 ? 0 : 32)) + q4);
            stageA4(As, row, q4, v);
        }
#pragma unroll
        for (int i = 0; i < 8; i++) {
            int idx = tid + i * 256;
            int n = idx >> 3, q4 = idx & 7;
            int oo = n >> 1, m = n & 1;
            float4 v = make_float4(0.f, 0.f, 0.f, 0.f);
            if (oo < nav) {
                int og = obase + oo;
                if (c < 4)
                    v = __ldg((const float4*)((m ? Wf : Wg) + (size_t)og * 128 + c * 32) + q4);
                else if (c == 4) {
                    if (!m) v = __ldg((const float4*)(Ag + (size_t)og * 32) + q4);
                } else {
                    if (m) v = __ldg((const float4*)(Af + (size_t)og * 32) + q4);
                }
            }
            stageB4<32>(Bs, n, q4, v);
        }
    };
    auto compute = [&](int buf) {
        const float* As = Abuf[buf];
        const float* Bs = Bbuf[buf];
#pragma unroll
        for (int k8 = 0; k8 < 4; k8++) {
            uint32_t a[2][4], bf[8][2];
#pragma unroll
            for (int mi2 = 0; mi2 < 2; mi2++) ldfragA(a[mi2], As, k8, wm * 2 + mi2, lane);
#pragma unroll
            for (int ni2 = 0; ni2 < 8; ni2++) ldfragB<32>(bf[ni2], Bs, k8, wn * 8 + ni2, lane);
#pragma unroll
            for (int mi2 = 0; mi2 < 2; mi2++)
#pragma unroll
                for (int ni2 = 0; ni2 < 8; ni2++) mma168(acc[mi2][ni2], a[mi2], bf[ni2]);
        }
    };

    stage(0, 0);
    __syncthreads();
    for (int c = 0; c < 6; c++) {
        int buf = c & 1;
        if (c < 5) stage(c + 1, buf ^ 1);
        compute(buf);
        __syncthreads();
    }

#pragma unroll
    for (int mi2 = 0; mi2 < 2; mi2++)
#pragma unroll
        for (int ni2 = 0; ni2 < 8; ni2++) {
            int oo = wn * 32 + ni2 * 4 + (lane & 3);
            if (oo < nav) {
                int r0 = t0 + wm * 32 + mi2 * 16 + (lane >> 2);
                float g0 = acc[mi2][ni2][0], f0 = acc[mi2][ni2][1];
                FF[(size_t)r0 * 2816 + obase + oo] = g0 * sigf(g0) * f0;
                int r1 = r0 + 8;
                float g1 = acc[mi2][ni2][2], f1 = acc[mi2][ni2][3];
                FF[(size_t)r1 * 2816 + obase + oo] = g1 * sigf(g1) * f1;
            }
        }
}

// ---------------------------------------------------------------------------
// k_out_m: CTA = 64 tokens x block b. N=128, K=384 = [FF_b(352)|R(32)].
// Epilogue: out = h + y.
// smem: A 8K x2 + B 16K x2 = 49152 B
// ---------------------------------------------------------------------------
#define OUT_SMEM 49152
__global__ __launch_bounds__(256, 2)
void k_out_m(const float* __restrict__ FF, const float* __restrict__ Rg,
             const float* __restrict__ Wp, const float* __restrict__ Ap,
             const float* __restrict__ hin, float* __restrict__ outp) {
    extern __shared__ float sm[];
    float* Abuf[2] = { sm, sm + 2048 };
    float* Bbuf[2] = { sm + 4096, sm + 8192 };
    const int tid = threadIdx.x, lane = tid & 31, wid = tid >> 5;
    const int wm = wid >> 2, wn = wid & 3;
    const int t0 = blockIdx.x * 64, b = blockIdx.y, ob = b * 128;

    float acc[2][4][4];
#pragma unroll
    for (int i = 0; i < 2; i++)
#pragma unroll
        for (int j = 0; j < 4; j++)
#pragma unroll
            for (int k = 0; k < 4; k++) acc[i][j][k] = 0.0f;

    auto stage = [&](int c, int buf) {
        float* As = Abuf[buf];
        float* Bs = Bbuf[buf];
#pragma unroll
        for (int i = 0; i < 2; i++) {
            int idx = tid + i * 256;
            int row = idx >> 3, q4 = idx & 7;
            int tok = t0 + row;
            float4 v;
            if (c < 11)
                v = __ldg((const float4*)(FF + (size_t)tok * 2816 + b * 352 + c * 32) + q4);
            else
                v = __ldg((const float4*)(Rg + (size_t)tok * 64) + q4);
            stageA4(As, row, q4, v);
        }
#pragma unroll
        for (int i = 0; i < 4; i++) {
            int idx = tid + i * 256;                  // 1024 float4s
            int n = idx >> 3, q4 = idx & 7;
            float4 v;
            if (c < 11)
                v = __ldg((const float4*)(Wp + (size_t)(ob + n) * 352 + c * 32) + q4);
            else
                v = __ldg((const float4*)(Ap + (size_t)(ob + n) * 32) + q4);
            stageB4<16>(Bs, n, q4, v);
        }
    };
    auto compute = [&](int buf) {
        const float* As = Abuf[buf];
        const float* Bs = Bbuf[buf];
#pragma unroll
        for (int k8 = 0; k8 < 4; k8++) {
            uint32_t a[2][4], bf[4][2];
#pragma unroll
            for (int mi2 = 0; mi2 < 2; mi2++) ldfragA(a[mi2], As, k8, wm * 2 + mi2, lane);
#pragma unroll
            for (int ni2 = 0; ni2 < 4; ni2++) ldfragB<16>(bf[ni2], Bs, k8, wn * 4 + ni2, lane);
#pragma unroll
            for (int mi2 = 0; mi2 < 2; mi2++)
#pragma unroll
                for (int ni2 = 0; ni2 < 4; ni2++) mma168(acc[mi2][ni2], a[mi2], bf[ni2]);
        }
    };

    stage(0, 0);
    __syncthreads();
    for (int c = 0; c < 12; c++) {
        int buf = c & 1;
        if (c < 11) stage(c + 1, buf ^ 1);
        compute(buf);
        __syncthreads();
    }

#pragma unroll
    for (int mi2 = 0; mi2 < 2; mi2++)
#pragma unroll
        for (int ni2 = 0; ni2 < 4; ni2++) {
            int r0 = t0 + wm * 32 + mi2 * 16 + (lane >> 2);
            int o  = ob + wn * 32 + ni2 * 8 + 2 * (lane & 3);
            float2 h0 = *(const float2*)(hin + (size_t)r0 * 1024 + o);
            *(float2*)(outp + (size_t)r0 * 1024 + o) =
                make_float2(h0.x + acc[mi2][ni2][0], h0.y + acc[mi2][ni2][1]);
            int r1 = r0 + 8;
            float2 h1 = *(const float2*)(hin + (size_t)r1 * 1024 + o);
            *(float2*)(outp + (size_t)r1 * 1024 + o) =
                make_float2(h1.x + acc[mi2][ni2][2], h1.y + acc[mi2][ni2][3]);
        }
}

// ---------------------------------------------------------------------------
// Host launcher
// ---------------------------------------------------------------------------
extern "C" void kernel_launch(void* const* d_in, const int* in_sizes, int n_in,
                              void* d_out, int out_size) {
    const float* x    = (const float*)d_in[0];
    const float* fgW  = (const float*)d_in[1];
    const float* fgA  = (const float*)d_in[2];
    const float* fgB  = (const float*)d_in[3];
    const float* guW  = (const float*)d_in[4];
    const float* guA  = (const float*)d_in[5];
    const float* guB  = (const float*)d_in[6];
    const float* ffgW = (const float*)d_in[7];
    const float* ffgA = (const float*)d_in[8];
    const float* ffgB = (const float*)d_in[9];
    const float* fffW = (const float*)d_in[10];
    const float* fffA = (const float*)d_in[11];
    const float* fffB = (const float*)d_in[12];
    const float* ffpW = (const float*)d_in[13];
    const float* ffpA = (const float*)d_in[14];
    const float* ffpB = (const float*)d_in[15];
    float* outp = (float*)d_out;

    float *H, *Z, *Rr, *FF;
    cudaGetSymbolAddress((void**)&H,  g_H);
    cudaGetSymbolAddress((void**)&Z,  g_Z);
    cudaGetSymbolAddress((void**)&Rr, g_R);
    cudaGetSymbolAddress((void**)&FF, g_FF);

    cudaFuncSetAttribute(k_iter_m, cudaFuncAttributeMaxDynamicSharedMemorySize, ITER_SMEM);
    cudaFuncSetAttribute(k_ff_m,   cudaFuncAttributeMaxDynamicSharedMemorySize, ITER_SMEM);
    cudaFuncSetAttribute(k_out_m,  cudaFuncAttributeMaxDynamicSharedMemorySize, OUT_SMEM);

    const float* hcur = x;
    for (int it = 0; it < 4; it++) {
        k_rms<<<NTOK, 256>>>(hcur, Z);
        k_rank<64, 2048, 1024, true><<<NTOK / 128, 256>>>(Z, fgB, guB, Rr);
        k_iter_m<<<dim3(NTOK / 64, 8), 256, ITER_SMEM>>>(Z, Rr, fgW, guW, fgA, guA, hcur, H);
        hcur = H;
    }
    k_rms<<<NTOK, 256>>>(H, Z);
    k_rank<64, 1024, 1024, false><<<NTOK / 128, 256>>>(Z, ffgB, fffB, Rr);
    k_ff_m<<<dim3(NTOK / 64, 8, 3), 256, ITER_SMEM>>>(Z, Rr, ffgW, fffW, ffgA, fffA, FF);
    k_rank<32, 2816, 2816, false><<<NTOK / 128, 256>>>(FF, ffpB, ffpB, Rr);
    k_out_m<<<dim3(NTOK / 64, 8), 256, OUT_SMEM>>>(FF, Rr, ffpW, ffpA, H, outp);
}

// round 6
// speedup vs baseline: 5.2749x; 1.7539x over previous
#include <cuda_runtime.h>
#include <cuda_bf16.h>
#include <math.h>
#include <stdint.h>

// ---------------------------------------------------------------------------
// IterativeBlock on GB300, compute_103-safe.
// Dense GEMMs + rank-32 projections: warp-level mma.sync tf32 (m16n8k8) with
// ldmatrix-based fragment loads.  rmsnorm scalar.
//
//   4x { z = rmsnorm(h); combined = [z, shift(z)];
//        h += sigmoid(ls_fg(combined)) * ls_gu(combined) }
//   z = rmsnorm(h); ff = silu(ls_ffg(z)) * ls_fff(z); out = h + ls_ffp(ff)
//   ls(x) = blockdiag(W) x + A (B x), NUM_BLOCKS = 8
//
// Tile storage: 128-byte ldmatrix blocks = 8 rows x 4 tf32.  A-side block id
// bidA = ((mi*2+mh)*K8 + k8)*2 + kh,  B-side bidB = (ni*K8 + k8)*2 + r.
// Row within block is XOR-swizzled by (bid & 7): staging STS.128 and
// ldmatrix.x4 reads are both bank-conflict-free.
// ---------------------------------------------------------------------------

#define NTOK 16384
#define EPSF 1.1920929e-07f

__device__ float g_H [NTOK * 1024];
__device__ float g_Z [NTOK * 1024];
__device__ float g_R [NTOK * 64];
__device__ float g_FF[NTOK * 2816];

__device__ __forceinline__ float sigf(float x) { return 1.0f / (1.0f + __expf(-x)); }

__device__ __forceinline__ uint32_t cvt_tf32(float f) {
    uint32_t r; asm("cvt.rna.tf32.f32 %0, %1;" : "=r"(r) : "f"(f)); return r;
}
__device__ __forceinline__ uint32_t s2u(const void* p) {
    return (uint32_t)__cvta_generic_to_shared(p);
}
__device__ __forceinline__ void ldsm4(uint32_t& r0, uint32_t& r1, uint32_t& r2, uint32_t& r3,
                                      uint32_t addr) {
    asm volatile("ldmatrix.sync.aligned.m8n8.x4.shared.b16 {%0,%1,%2,%3}, [%4];"
                 : "=r"(r0), "=r"(r1), "=r"(r2), "=r"(r3) : "r"(addr));
}
__device__ __forceinline__ void mma168(float* c, const uint32_t* a, const uint32_t* b) {
    asm volatile(
        "mma.sync.aligned.m16n8k8.row.col.f32.tf32.tf32.f32 "
        "{%0,%1,%2,%3}, {%4,%5,%6,%7}, {%8,%9}, {%0,%1,%2,%3};"
        : "+f"(c[0]), "+f"(c[1]), "+f"(c[2]), "+f"(c[3])
        : "r"(a[0]), "r"(a[1]), "r"(a[2]), "r"(a[3]), "r"(b[0]), "r"(b[1]));
}

// ---- tile staging / fragment loads ----------------------------------------
template<int K8>
__device__ __forceinline__ void stA(uint32_t base, int row, int q4, float4 v) {
    int k8 = q4 >> 1, kh = q4 & 1;
    int m8 = row & 7, mh = (row >> 3) & 1, mi = row >> 4;
    int bid = ((mi * 2 + mh) * K8 + k8) * 2 + kh;
    int r = m8 ^ (bid & 7);
    uint32_t addr = base + (uint32_t)(bid * 128 + r * 16);
    asm volatile("st.shared.v4.b32 [%0], {%1,%2,%3,%4};" :: "r"(addr),
                 "r"(cvt_tf32(v.x)), "r"(cvt_tf32(v.y)),
                 "r"(cvt_tf32(v.z)), "r"(cvt_tf32(v.w)) : "memory");
}
template<int K8>
__device__ __forceinline__ void stB(uint32_t base, int n, int q4, float4 v) {
    int k8 = q4 >> 1, r = q4 & 1;
    int n8 = n & 7, ni = n >> 3;
    int bid = (ni * K8 + k8) * 2 + r;
    int rr = n8 ^ (bid & 7);
    uint32_t addr = base + (uint32_t)(bid * 128 + rr * 16);
    asm volatile("st.shared.v4.b32 [%0], {%1,%2,%3,%4};" :: "r"(addr),
                 "r"(cvt_tf32(v.x)), "r"(cvt_tf32(v.y)),
                 "r"(cvt_tf32(v.z)), "r"(cvt_tf32(v.w)) : "memory");
}
template<int K8>
__device__ __forceinline__ void ldA(uint32_t* a, uint32_t base, int k8, int mi, int lane) {
    int j = lane >> 3, mh = j & 1, kh = j >> 1;
    int bid = ((mi * 2 + mh) * K8 + k8) * 2 + kh;
    int r = (lane & 7) ^ (bid & 7);
    ldsm4(a[0], a[1], a[2], a[3], base + (uint32_t)(bid * 128 + r * 16));
}
template<int K8>
__device__ __forceinline__ void ldB(uint32_t* b0, uint32_t* b1, uint32_t base,
                                    int k8, int ni0, int lane) {
    int j = lane >> 3, nio = j >> 1, r = j & 1;
    int bid = ((ni0 + nio) * K8 + k8) * 2 + r;
    int rr = (lane & 7) ^ (bid & 7);
    ldsm4(b0[0], b0[1], b1[0], b1[1], base + (uint32_t)(bid * 128 + rr * 16));
}

// ---------------------------------------------------------------------------
// k_rms: one CTA per token.
// ---------------------------------------------------------------------------
__global__ __launch_bounds__(256)
void k_rms(const float* __restrict__ h, float* __restrict__ z) {
    __shared__ float ws[8];
    const int t = blockIdx.x, tid = threadIdx.x;
    float4 v = __ldg((const float4*)(h + (size_t)t * 1024) + tid);
    float s = v.x * v.x + v.y * v.y + v.z * v.z + v.w * v.w;
#pragma unroll
    for (int off = 16; off; off >>= 1) s += __shfl_xor_sync(0xffffffffu, s, off);
    if ((tid & 31) == 0) ws[tid >> 5] = s;
    __syncthreads();
    if (tid < 32) {
        float x2 = (tid < 8) ? ws[tid] : 0.0f;
#pragma unroll
        for (int off = 4; off; off >>= 1) x2 += __shfl_xor_sync(0xffffffffu, x2, off);
        if (tid == 0) ws[0] = rsqrtf(x2 * (1.0f / 1024.0f) + EPSF);
    }
    __syncthreads();
    const float inv = ws[0];
    *((float4*)(z + (size_t)t * 1024) + tid) =
        make_float4(v.x * inv, v.y * inv, v.z * inv, v.w * inv);
}

// ---------------------------------------------------------------------------
// k_rank_m: R[t, 0:NO] = [B1;B2] @ in_t   (MMA tf32)
// in_t = [Z[t], Z[t-1]] if SHIFT else src[t].  CTA = 64 tokens, K-chunk 64.
// 256 threads, 8 warps = 4(m) x 2(n): warp tile 16 tokens x (NO/2) outs.
// ---------------------------------------------------------------------------
template<int NO, int KD, int SRCS, bool SHIFT>
__global__ __launch_bounds__(256)
void k_rank_m(const float* __restrict__ src,
              const float* __restrict__ B1, const float* __restrict__ B2,
              float* __restrict__ R) {
    constexpr int K8 = 8;                 // K-chunk 64 = 8 k8 steps
    constexpr int NI = NO / 8;
    constexpr int NIW = NI / 2;           // ni per warp (WN = 2)
    constexpr int ABYT = 4 * K8 * 4 * 128;        // MI=4 -> 16 KB
    constexpr int BBYT = NI * K8 * 2 * 128;       // 16 KB (NO=64) / 8 KB (NO=32)
    constexpr int NC = KD / 64;
    extern __shared__ float sm[];
    const uint32_t sbase = s2u(sm);
    const uint32_t Ab[2] = { sbase, sbase + ABYT };
    const uint32_t Bb[2] = { sbase + 2 * ABYT, sbase + 2 * ABYT + BBYT };
    const int tid = threadIdx.x, lane = tid & 31, wid = tid >> 5;
    const int wm = wid >> 1, wn = wid & 1;
    const int t0 = blockIdx.x * 64;

    float acc[NIW][4];
#pragma unroll
    for (int j = 0; j < NIW; j++)
#pragma unroll
        for (int i = 0; i < 4; i++) acc[j][i] = 0.0f;

    auto stage = [&](int c, int buf) {
        int roff = 0, colb = c * 64;
        if (SHIFT && colb >= 1024) { roff = -1; colb -= 1024; }
#pragma unroll
        for (int i = 0; i < 4; i++) {                 // A: 64 rows x 16 q4
            int idx = tid + i * 256;
            int row = idx >> 4, q4 = idx & 15;
            int tok = t0 + row;
            float4 v = make_float4(0.f, 0.f, 0.f, 0.f);
            if (!SHIFT || roff == 0 || (tok & 2047) != 0)
                v = __ldg((const float4*)(src + (size_t)(tok + roff) * SRCS + colb) + q4);
            stA<K8>(Ab[buf], row, q4, v);
        }
#pragma unroll
        for (int i = 0; i < NO / 16; i++) {           // B: NO rows x 16 q4
            int idx = tid + i * 256;
            int n = idx >> 4, q4 = idx & 15;
            const float* Bp = (n < 32) ? (B1 + (size_t)n * KD)
                                       : (B2 + (size_t)(n - 32) * KD);
            float4 v = __ldg((const float4*)(Bp + c * 64) + q4);
            stB<K8>(Bb[buf], n, q4, v);
        }
    };
    auto compute = [&](int buf) {
#pragma unroll
        for (int k8 = 0; k8 < K8; k8++) {
            uint32_t a[4], bf[NIW][2];
            ldA<K8>(a, Ab[buf], k8, wm, lane);
#pragma unroll
            for (int n2 = 0; n2 < NIW; n2 += 2)
                ldB<K8>(bf[n2], bf[n2 + 1], Bb[buf], k8, wn * NIW + n2, lane);
#pragma unroll
            for (int n2 = 0; n2 < NIW; n2++) mma168(acc[n2], a, bf[n2]);
        }
    };

    stage(0, 0);
    __syncthreads();
    for (int c = 0; c < NC; c++) {
        int buf = c & 1;
        if (c + 1 < NC) stage(c + 1, buf ^ 1);
        compute(buf);
        __syncthreads();
    }

#pragma unroll
    for (int n2 = 0; n2 < NIW; n2++) {
        int r0 = t0 + wm * 16 + (lane >> 2);
        int o  = wn * (NO / 2) + n2 * 8 + 2 * (lane & 3);
        *(float2*)(R + (size_t)r0 * 64 + o) = make_float2(acc[n2][0], acc[n2][1]);
        *(float2*)(R + (size_t)(r0 + 8) * 64 + o) = make_float2(acc[n2][2], acc[n2][3]);
    }
}

// ---------------------------------------------------------------------------
// k_iter_m: CTA = 128 tokens x block b.  Fused N=256 (n=2o+m: m=0 fg, m=1 gu),
// K=320 = [Z_b(256) | Rg(32) | Ru(32)].  512 threads = 4(m) x 4(n) warps.
// Epilogue: h += sigmoid(g) * u.
// smem: A 16K x2 + B 32K x2 = 96 KB
// ---------------------------------------------------------------------------
#define ITER_SMEM 98304
__global__ __launch_bounds__(512, 1)
void k_iter_m(const float* __restrict__ Z, const float* __restrict__ Rg,
              const float* __restrict__ Wg, const float* __restrict__ Wu,
              const float* __restrict__ Ag, const float* __restrict__ Au,
              const float* __restrict__ hin, float* __restrict__ hout) {
    constexpr int K8 = 4;
    extern __shared__ float sm[];
    const uint32_t sbase = s2u(sm);
    const uint32_t Ab[2] = { sbase, sbase + 16384 };
    const uint32_t Bb[2] = { sbase + 32768, sbase + 65536 };
    const int tid = threadIdx.x, lane = tid & 31, wid = tid >> 5;
    const int wm = wid >> 2, wn = wid & 3;
    const int t0 = blockIdx.x * 128, b = blockIdx.y;
    const int roff = (b < 4) ? 0 : -1, cbase = (b & 3) * 256, ob = b * 128;

    float acc[2][8][4];
#pragma unroll
    for (int i = 0; i < 2; i++)
#pragma unroll
        for (int j = 0; j < 8; j++)
#pragma unroll
            for (int k = 0; k < 4; k++) acc[i][j][k] = 0.0f;

    auto stage = [&](int c, int buf) {
#pragma unroll
        for (int i = 0; i < 2; i++) {                 // A: 128 rows x 8 q4
            int idx = tid + i * 512;
            int row = idx >> 3, q4 = idx & 7;
            int tok = t0 + row;
            float4 v = make_float4(0.f, 0.f, 0.f, 0.f);
            if (c < 8) {
                if (roff == 0 || (tok & 2047) != 0)
                    v = __ldg((const float4*)(Z + (size_t)(tok + roff) * 1024 + cbase + c * 32) + q4);
            } else {
                v = __ldg((const float4*)(Rg + (size_t)tok * 64 + (c - 8) * 32) + q4);
            }
            stA<K8>(Ab[buf], row, q4, v);
        }
#pragma unroll
        for (int i = 0; i < 4; i++) {                 // B: 256 rows x 8 q4
            int idx = tid + i * 512;
            int n = idx >> 3, q4 = idx & 7;
            int o = n >> 1, m = n & 1;
            float4 v = make_float4(0.f, 0.f, 0.f, 0.f);
            if (c < 8) {
                v = __ldg((const float4*)((m ? Wu : Wg) + (size_t)(ob + o) * 256 + c * 32) + q4);
            } else if (c == 8) {
                if (!m) v = __ldg((const float4*)(Ag + (size_t)(ob + o) * 32) + q4);
            } else {
                if (m) v = __ldg((const float4*)(Au + (size_t)(ob + o) * 32) + q4);
            }
            stB<K8>(Bb[buf], n, q4, v);
        }
    };
    auto compute = [&](int buf) {
#pragma unroll
        for (int k8 = 0; k8 < K8; k8++) {
            uint32_t a[2][4], bf[8][2];
#pragma unroll
            for (int mi2 = 0; mi2 < 2; mi2++) ldA<K8>(a[mi2], Ab[buf], k8, wm * 2 + mi2, lane);
#pragma unroll
            for (int n2 = 0; n2 < 8; n2 += 2)
                ldB<K8>(bf[n2], bf[n2 + 1], Bb[buf], k8, wn * 8 + n2, lane);
#pragma unroll
            for (int mi2 = 0; mi2 < 2; mi2++)
#pragma unroll
                for (int n2 = 0; n2 < 8; n2++) mma168(acc[mi2][n2], a[mi2], bf[n2]);
        }
    };

    stage(0, 0);
    __syncthreads();
    for (int c = 0; c < 10; c++) {
        int buf = c & 1;
        if (c < 9) stage(c + 1, buf ^ 1);
        compute(buf);
        __syncthreads();
    }

#pragma unroll
    for (int mi2 = 0; mi2 < 2; mi2++)
#pragma unroll
        for (int n2 = 0; n2 < 8; n2++) {
            int r0 = t0 + wm * 32 + mi2 * 16 + (lane >> 2);
            int o  = ob + wn * 32 + n2 * 4 + (lane & 3);
            float g0 = acc[mi2][n2][0], u0 = acc[mi2][n2][1];
            hout[(size_t)r0 * 1024 + o] = hin[(size_t)r0 * 1024 + o] + sigf(g0) * u0;
            int r1 = r0 + 8;
            float g1 = acc[mi2][n2][2], u1 = acc[mi2][n2][3];
            hout[(size_t)r1 * 1024 + o] = hin[(size_t)r1 * 1024 + o] + sigf(g1) * u1;
        }
}

// ---------------------------------------------------------------------------
// k_ff_m: CTA = 128 tokens x block b x slice ot (outs {128,128,96}).
// Fused N=256 (n=2oo+m: m=0 ffg, m=1 fff), K=192 = [Z_b(128)|Rg(32)|Rf(32)].
// Epilogue: FF = silu(g) * f.
// ---------------------------------------------------------------------------
__global__ __launch_bounds__(512, 1)
void k_ff_m(const float* __restrict__ Z, const float* __restrict__ Rg,
            const float* __restrict__ Wg, const float* __restrict__ Wf,
            const float* __restrict__ Ag, const float* __restrict__ Af,
            float* __restrict__ FF) {
    constexpr int K8 = 4;
    extern __shared__ float sm[];
    const uint32_t sbase = s2u(sm);
    const uint32_t Ab[2] = { sbase, sbase + 16384 };
    const uint32_t Bb[2] = { sbase + 32768, sbase + 65536 };
    const int tid = threadIdx.x, lane = tid & 31, wid = tid >> 5;
    const int wm = wid >> 2, wn = wid & 3;
    const int t0 = blockIdx.x * 128, b = blockIdx.y, ot = blockIdx.z;
    const int nav = (ot == 2) ? 96 : 128;
    const int obase = b * 352 + ot * 128;

    float acc[2][8][4];
#pragma unroll
    for (int i = 0; i < 2; i++)
#pragma unroll
        for (int j = 0; j < 8; j++)
#pragma unroll
            for (int k = 0; k < 4; k++) acc[i][j][k] = 0.0f;

    auto stage = [&](int c, int buf) {
#pragma unroll
        for (int i = 0; i < 2; i++) {
            int idx = tid + i * 512;
            int row = idx >> 3, q4 = idx & 7;
            int tok = t0 + row;
            float4 v;
            if (c < 4)
                v = __ldg((const float4*)(Z + (size_t)tok * 1024 + b * 128 + c * 32) + q4);
            else
                v = __ldg((const float4*)(Rg + (size_t)tok * 64 + (c - 4) * 32) + q4);
            stA<K8>(Ab[buf], row, q4, v);
        }
#pragma unroll
        for (int i = 0; i < 4; i++) {
            int idx = tid + i * 512;
            int n = idx >> 3, q4 = idx & 7;
            int oo = n >> 1, m = n & 1;
            float4 v = make_float4(0.f, 0.f, 0.f, 0.f);
            if (oo < nav) {
                int og = obase + oo;
                if (c < 4)
                    v = __ldg((const float4*)((m ? Wf : Wg) + (size_t)og * 128 + c * 32) + q4);
                else if (c == 4) {
                    if (!m) v = __ldg((const float4*)(Ag + (size_t)og * 32) + q4);
                } else {
                    if (m) v = __ldg((const float4*)(Af + (size_t)og * 32) + q4);
                }
            }
            stB<K8>(Bb[buf], n, q4, v);
        }
    };
    auto compute = [&](int buf) {
#pragma unroll
        for (int k8 = 0; k8 < K8; k8++) {
            uint32_t a[2][4], bf[8][2];
#pragma unroll
            for (int mi2 = 0; mi2 < 2; mi2++) ldA<K8>(a[mi2], Ab[buf], k8, wm * 2 + mi2, lane);
#pragma unroll
            for (int n2 = 0; n2 < 8; n2 += 2)
                ldB<K8>(bf[n2], bf[n2 + 1], Bb[buf], k8, wn * 8 + n2, lane);
#pragma unroll
            for (int mi2 = 0; mi2 < 2; mi2++)
#pragma unroll
                for (int n2 = 0; n2 < 8; n2++) mma168(acc[mi2][n2], a[mi2], bf[n2]);
        }
    };

    stage(0, 0);
    __syncthreads();
    for (int c = 0; c < 6; c++) {
        int buf = c & 1;
        if (c < 5) stage(c + 1, buf ^ 1);
        compute(buf);
        __syncthreads();
    }

#pragma unroll
    for (int mi2 = 0; mi2 < 2; mi2++)
#pragma unroll
        for (int n2 = 0; n2 < 8; n2++) {
            int oo = wn * 32 + n2 * 4 + (lane & 3);
            if (oo < nav) {
                int r0 = t0 + wm * 32 + mi2 * 16 + (lane >> 2);
                float g0 = acc[mi2][n2][0], f0 = acc[mi2][n2][1];
                FF[(size_t)r0 * 2816 + obase + oo] = g0 * sigf(g0) * f0;
                int r1 = r0 + 8;
                float g1 = acc[mi2][n2][2], f1 = acc[mi2][n2][3];
                FF[(size_t)r1 * 2816 + obase + oo] = g1 * sigf(g1) * f1;
            }
        }
}

// ---------------------------------------------------------------------------
// k_out_m: CTA = 128 tokens x block b.  N=128, K=384 = [FF_b(352)|R(32)].
// Epilogue: out = h + y.  smem: A 16K x2 + B 16K x2 = 64 KB.
// ---------------------------------------------------------------------------
#define OUT_SMEM 65536
__global__ __launch_bounds__(512, 1)
void k_out_m(const float* __restrict__ FF, const float* __restrict__ Rg,
             const float* __restrict__ Wp, const float* __restrict__ Ap,
             const float* __restrict__ hin, float* __restrict__ outp) {
    constexpr int K8 = 4;
    extern __shared__ float sm[];
    const uint32_t sbase = s2u(sm);
    const uint32_t Ab[2] = { sbase, sbase + 16384 };
    const uint32_t Bb[2] = { sbase + 32768, sbase + 49152 };
    const int tid = threadIdx.x, lane = tid & 31, wid = tid >> 5;
    const int wm = wid >> 2, wn = wid & 3;
    const int t0 = blockIdx.x * 128, b = blockIdx.y, ob = b * 128;

    float acc[2][4][4];
#pragma unroll
    for (int i = 0; i < 2; i++)
#pragma unroll
        for (int j = 0; j < 4; j++)
#pragma unroll
            for (int k = 0; k < 4; k++) acc[i][j][k] = 0.0f;

    auto stage = [&](int c, int buf) {
#pragma unroll
        for (int i = 0; i < 2; i++) {
            int idx = tid + i * 512;
            int row = idx >> 3, q4 = idx & 7;
            int tok = t0 + row;
            float4 v;
            if (c < 11)
                v = __ldg((const float4*)(FF + (size_t)tok * 2816 + b * 352 + c * 32) + q4);
            else
                v = __ldg((const float4*)(Rg + (size_t)tok * 64) + q4);
            stA<K8>(Ab[buf], row, q4, v);
        }
#pragma unroll
        for (int i = 0; i < 2; i++) {                 // B: 128 rows x 8 q4
            int idx = tid + i * 512;
            int n = idx >> 3, q4 = idx & 7;
            float4 v;
            if (c < 11)
                v = __ldg((const float4*)(Wp + (size_t)(ob + n) * 352 + c * 32) + q4);
            else
                v = __ldg((const float4*)(Ap + (size_t)(ob + n) * 32) + q4);
            stB<K8>(Bb[buf], n, q4, v);
        }
    };
    auto compute = [&](int buf) {
#pragma unroll
        for (int k8 = 0; k8 < K8; k8++) {
            uint32_t a[2][4], bf[4][2];
#pragma unroll
            for (int mi2 = 0; mi2 < 2; mi2++) ldA<K8>(a[mi2], Ab[buf], k8, wm * 2 + mi2, lane);
#pragma unroll
            for (int n2 = 0; n2 < 4; n2 += 2)
                ldB<K8>(bf[n2], bf[n2 + 1], Bb[buf], k8, wn * 4 + n2, lane);
#pragma unroll
            for (int mi2 = 0; mi2 < 2; mi2++)
#pragma unroll
                for (int n2 = 0; n2 < 4; n2++) mma168(acc[mi2][n2], a[mi2], bf[n2]);
        }
    };

    stage(0, 0);
    __syncthreads();
    for (int c = 0; c < 12; c++) {
        int buf = c & 1;
        if (c < 11) stage(c + 1, buf ^ 1);
        compute(buf);
        __syncthreads();
    }

#pragma unroll
    for (int mi2 = 0; mi2 < 2; mi2++)
#pragma unroll
        for (int n2 = 0; n2 < 4; n2++) {
            int r0 = t0 + wm * 32 + mi2 * 16 + (lane >> 2);
            int o  = ob + wn * 32 + n2 * 8 + 2 * (lane & 3);
            float2 h0 = *(const float2*)(hin + (size_t)r0 * 1024 + o);
            *(float2*)(outp + (size_t)r0 * 1024 + o) =
                make_float2(h0.x + acc[mi2][n2][0], h0.y + acc[mi2][n2][1]);
            int r1 = r0 + 8;
            float2 h1 = *(const float2*)(hin + (size_t)r1 * 1024 + o);
            *(float2*)(outp + (size_t)r1 * 1024 + o) =
                make_float2(h1.x + acc[mi2][n2][2], h1.y + acc[mi2][n2][3]);
        }
}

// ---------------------------------------------------------------------------
// Host launcher
// ---------------------------------------------------------------------------
#define RANK64_SMEM 65536
#define RANK32_SMEM 49152

extern "C" void kernel_launch(void* const* d_in, const int* in_sizes, int n_in,
                              void* d_out, int out_size) {
    const float* x    = (const float*)d_in[0];
    const float* fgW  = (const float*)d_in[1];
    const float* fgA  = (const float*)d_in[2];
    const float* fgB  = (const float*)d_in[3];
    const float* guW  = (const float*)d_in[4];
    const float* guA  = (const float*)d_in[5];
    const float* guB  = (const float*)d_in[6];
    const float* ffgW = (const float*)d_in[7];
    const float* ffgA = (const float*)d_in[8];
    const float* ffgB = (const float*)d_in[9];
    const float* fffW = (const float*)d_in[10];
    const float* fffA = (const float*)d_in[11];
    const float* fffB = (const float*)d_in[12];
    const float* ffpW = (const float*)d_in[13];
    const float* ffpA = (const float*)d_in[14];
    const float* ffpB = (const float*)d_in[15];
    float* outp = (float*)d_out;

    float *H, *Z, *Rr, *FF;
    cudaGetSymbolAddress((void**)&H,  g_H);
    cudaGetSymbolAddress((void**)&Z,  g_Z);
    cudaGetSymbolAddress((void**)&Rr, g_R);
    cudaGetSymbolAddress((void**)&FF, g_FF);

    cudaFuncSetAttribute(k_iter_m, cudaFuncAttributeMaxDynamicSharedMemorySize, ITER_SMEM);
    cudaFuncSetAttribute(k_ff_m,   cudaFuncAttributeMaxDynamicSharedMemorySize, ITER_SMEM);
    cudaFuncSetAttribute(k_out_m,  cudaFuncAttributeMaxDynamicSharedMemorySize, OUT_SMEM);
    cudaFuncSetAttribute(k_rank_m<64, 2048, 1024, true>,
                         cudaFuncAttributeMaxDynamicSharedMemorySize, RANK64_SMEM);
    cudaFuncSetAttribute(k_rank_m<64, 1024, 1024, false>,
                         cudaFuncAttributeMaxDynamicSharedMemorySize, RANK64_SMEM);
    cudaFuncSetAttribute(k_rank_m<32, 2816, 2816, false>,
                         cudaFuncAttributeMaxDynamicSharedMemorySize, RANK32_SMEM);

    const float* hcur = x;
    for (int it = 0; it < 4; it++) {
        k_rms<<<NTOK, 256>>>(hcur, Z);
        k_rank_m<64, 2048, 1024, true><<<NTOK / 64, 256, RANK64_SMEM>>>(Z, fgB, guB, Rr);
        k_iter_m<<<dim3(NTOK / 128, 8), 512, ITER_SMEM>>>(Z, Rr, fgW, guW, fgA, guA, hcur, H);
        hcur = H;
    }
    k_rms<<<NTOK, 256>>>(H, Z);
    k_rank_m<64, 1024, 1024, false><<<NTOK / 64, 256, RANK64_SMEM>>>(Z, ffgB, fffB, Rr);
    k_ff_m<<<dim3(NTOK / 128, 8, 3), 512, ITER_SMEM>>>(Z, Rr, ffgW, fffW, ffgA, fffA, FF);
    k_rank_m<32, 2816, 2816, false><<<NTOK / 64, 256, RANK32_SMEM>>>(FF, ffpB, ffpB, Rr);
    k_out_m<<<dim3(NTOK / 128, 8), 512, OUT_SMEM>>>(FF, Rr, ffpW, ffpA, H, outp);
}